// round 1
// baseline (speedup 1.0000x reference)
#include <cuda_runtime.h>
#include <cstdint>
#include <math.h>

#define Dm 1024
#define Hn 8
#define DHn 128
#define Fn 4096
#define Vn 16384
#define ENCn 438
#define PASTn 447
#define TOTn 448
#define Lnum 8
#define ATT_SCALE 0.08838834764831845f

// ---------------- device scratch (no allocations allowed) ----------------
__device__ float g_x[Dm];          // residual stream
__device__ float g_qkv[3 * Dm];    // self q,k,v
__device__ float g_att_o[Dm];      // attn output (self & cross o-proj reuse)
__device__ float g_qc[Dm];         // cross q
__device__ float g_t[Hn * Dm];     // t = q @ Wk^T per head
__device__ float g_sc[Hn * ENCn];  // cross scores
__device__ float g_a[Hn * ENCn];   // cross attn probs
__device__ float g_u[Hn * Dm];     // u = a @ E per head
__device__ float g_ffn[Fn];        // ffn hidden

__device__ __forceinline__ float gelu_f(float v) {
    float c = v * v * v;
    return 0.5f * v * (1.0f + tanhf(0.7978845608028654f * (v + 0.044715f * c)));
}

// ---------------- embedding ----------------
__global__ void embed_kernel(const int* __restrict__ ids,
                             const float* __restrict__ emb,
                             const float* __restrict__ pos) {
    int d = threadIdx.x;
    int id = ids[0];
    g_x[d] = emb[(size_t)id * Dm + d] + pos[(size_t)PASTn * Dm + d];
}

// ---------------- generic matvec: out[j] = sum_i x[i] * W[i*dout + j] -----
// 1024 threads: 8 outputs per block, 128 in-groups, deterministic smem reduce.
template <int DIN, bool LN, bool GELU, bool RES, bool PERHEAD>
__global__ void matvec_kernel(const float* __restrict__ W,
                              const float* __restrict__ xin,
                              const float* __restrict__ gamma,
                              const float* __restrict__ beta,
                              float* __restrict__ out,
                              int dout) {
    constexpr int SXN = PERHEAD ? 8 * Dm : DIN;
    __shared__ float sx[SXN];
    __shared__ float red[1024];
    int tid = threadIdx.x;

    if (PERHEAD) {
        for (int i = tid; i < 8 * Dm; i += 1024) sx[i] = xin[i];
        __syncthreads();
    } else if (LN) {
        // DIN == 1024 for LN paths
        float v = xin[tid];
        red[tid] = v;
        __syncthreads();
        #pragma unroll
        for (int s = 512; s >= 1; s >>= 1) {
            if (tid < s) red[tid] += red[tid + s];
            __syncthreads();
        }
        float mean = red[0] * (1.0f / 1024.0f);
        __syncthreads();
        float dv = v - mean;
        red[tid] = dv * dv;
        __syncthreads();
        #pragma unroll
        for (int s = 512; s >= 1; s >>= 1) {
            if (tid < s) red[tid] += red[tid + s];
            __syncthreads();
        }
        float var = red[0] * (1.0f / 1024.0f);
        __syncthreads();
        sx[tid] = dv * rsqrtf(var + 1e-5f) * gamma[tid] + beta[tid];
        __syncthreads();
    } else {
        for (int i = tid; i < DIN; i += 1024) sx[i] = xin[i];
        __syncthreads();
    }

    int jo = tid & 7, ig = tid >> 3;
    int j = blockIdx.x * 8 + jo;
    const float* xp = PERHEAD ? (sx + ((j >> 7) << 10)) : sx;
    float acc = 0.0f;
    #pragma unroll
    for (int r = 0; r < DIN / 128; r++) {
        int i = r * 128 + ig;
        acc += xp[i] * W[i * dout + j];
    }
    red[tid] = acc;
    __syncthreads();
    #pragma unroll
    for (int s = 64; s >= 1; s >>= 1) {
        if (ig < s) red[tid] += red[tid + s * 8];
        __syncthreads();
    }
    if (ig == 0) {
        float v = red[jo];
        if (GELU) v = gelu_f(v);
        if (RES) v += out[j];
        out[j] = v;
    }
}

// ---------------- fused LN1 + q/k/v self projections ----------------
// grid = 384 blocks: blocks [0,128)->q, [128,256)->k, [256,384)->v
__global__ void qkv3_kernel(const float* __restrict__ Wq,
                            const float* __restrict__ Wk,
                            const float* __restrict__ Wv,
                            const float* __restrict__ gamma,
                            const float* __restrict__ beta) {
    __shared__ float sx[Dm];
    __shared__ float red[1024];
    int tid = threadIdx.x;
    float v = g_x[tid];
    red[tid] = v;
    __syncthreads();
    #pragma unroll
    for (int s = 512; s >= 1; s >>= 1) {
        if (tid < s) red[tid] += red[tid + s];
        __syncthreads();
    }
    float mean = red[0] * (1.0f / 1024.0f);
    __syncthreads();
    float dv = v - mean;
    red[tid] = dv * dv;
    __syncthreads();
    #pragma unroll
    for (int s = 512; s >= 1; s >>= 1) {
        if (tid < s) red[tid] += red[tid + s];
        __syncthreads();
    }
    float var = red[0] * (1.0f / 1024.0f);
    __syncthreads();
    sx[tid] = dv * rsqrtf(var + 1e-5f) * gamma[tid] + beta[tid];
    __syncthreads();

    int m = blockIdx.x >> 7;
    int jb = blockIdx.x & 127;
    const float* W = (m == 0) ? Wq : ((m == 1) ? Wk : Wv);
    int jo = tid & 7, ig = tid >> 3;
    int j = jb * 8 + jo;
    float acc = 0.0f;
    #pragma unroll
    for (int r = 0; r < 8; r++) {
        int i = r * 128 + ig;
        acc += sx[i] * W[i * Dm + j];
    }
    red[tid] = acc;
    __syncthreads();
    #pragma unroll
    for (int s = 64; s >= 1; s >>= 1) {
        if (ig < s) red[tid] += red[tid + s * 8];
        __syncthreads();
    }
    if (ig == 0) g_qkv[m * Dm + j] = red[jo];
}

// ---------------- self attention over cached KV + new token --------------
// grid = 8 (one block per head), 1024 threads
__global__ void self_attn_kernel(const float* __restrict__ past_k,
                                 const float* __restrict__ past_v) {
    int h = blockIdx.x;
    int tid = threadIdx.x;
    __shared__ float q[DHn], kn[DHn], vn[DHn];
    __shared__ float sc[TOTn];
    __shared__ float red[1024];
    if (tid < DHn) {
        q[tid]  = g_qkv[h * DHn + tid];
        kn[tid] = g_qkv[Dm + h * DHn + tid];
        vn[tid] = g_qkv[2 * Dm + h * DHn + tid];
    }
    __syncthreads();

    int warp = tid >> 5, lane = tid & 31;
    for (int p = warp; p < TOTn; p += 32) {
        const float* krow = (p < PASTn)
            ? past_k + ((size_t)h * PASTn + p) * DHn
            : kn;
        float4 k4 = *(const float4*)(krow + lane * 4);
        float4 q4 = *(const float4*)(q + lane * 4);
        float d = k4.x * q4.x + k4.y * q4.y + k4.z * q4.z + k4.w * q4.w;
        #pragma unroll
        for (int s = 16; s >= 1; s >>= 1) d += __shfl_xor_sync(0xffffffffu, d, s);
        if (lane == 0) sc[p] = d * ATT_SCALE;
    }
    __syncthreads();

    // softmax over 448
    float m = (tid < TOTn) ? sc[tid] : -1e30f;
    red[tid] = m;
    __syncthreads();
    #pragma unroll
    for (int s = 512; s >= 1; s >>= 1) {
        if (tid < s) red[tid] = fmaxf(red[tid], red[tid + s]);
        __syncthreads();
    }
    m = red[0];
    __syncthreads();
    float e = (tid < TOTn) ? expf(sc[tid] - m) : 0.0f;
    red[tid] = e;
    __syncthreads();
    #pragma unroll
    for (int s = 512; s >= 1; s >>= 1) {
        if (tid < s) red[tid] += red[tid + s];
        __syncthreads();
    }
    float inv = 1.0f / red[0];
    __syncthreads();
    if (tid < TOTn) sc[tid] = e * inv;
    __syncthreads();

    // o[c] = sum_p a[p] * V[p][c]; 8 p-groups x 128 c
    int c = tid & 127, pg = tid >> 7;
    float acc = 0.0f;
    for (int p = pg; p < TOTn; p += 8) {
        float vv = (p < PASTn) ? past_v[((size_t)h * PASTn + p) * DHn + c] : vn[c];
        acc += sc[p] * vv;
    }
    red[tid] = acc;
    __syncthreads();
    #pragma unroll
    for (int s = 4; s >= 1; s >>= 1) {
        if (pg < s) red[tid] += red[tid + s * 128];
        __syncthreads();
    }
    if (pg == 0) g_att_o[h * DHn + c] = red[c];
}

// ---------------- cross attention: t[h][d] = q_h . wk_c[d, h*128..] ------
// warp per output, grid = 1024, block = 256
__global__ void t_kernel(const float* __restrict__ wk) {
    int gw = blockIdx.x * 8 + (threadIdx.x >> 5);
    int lane = threadIdx.x & 31;
    int h = gw >> 10, d = gw & 1023;
    float4 w4 = *(const float4*)(wk + (size_t)d * Dm + h * DHn + lane * 4);
    float4 q4 = *(const float4*)(g_qc + h * DHn + lane * 4);
    float acc = w4.x * q4.x + w4.y * q4.y + w4.z * q4.z + w4.w * q4.w;
    #pragma unroll
    for (int s = 16; s >= 1; s >>= 1) acc += __shfl_xor_sync(0xffffffffu, acc, s);
    if (lane == 0) g_t[gw] = acc;
}

// ---------------- cross scores: sc[h][e] = t[h] . E[e] * scale -----------
// warp per (h,e); grid = 438 blocks of 256 threads (3504 warps needed)
__global__ void scores_kernel(const float* __restrict__ E) {
    int gw = blockIdx.x * 8 + (threadIdx.x >> 5);
    int lane = threadIdx.x & 31;
    if (gw >= Hn * ENCn) return;
    int h = gw / ENCn, e = gw - h * ENCn;
    const float* erow = E + (size_t)e * Dm;
    const float* trow = g_t + h * Dm;
    float acc = 0.0f;
    #pragma unroll
    for (int r = 0; r < 8; r++) {
        int i = r * 128 + lane * 4;
        float4 e4 = *(const float4*)(erow + i);
        float4 t4 = *(const float4*)(trow + i);
        acc += e4.x * t4.x + e4.y * t4.y + e4.z * t4.z + e4.w * t4.w;
    }
    #pragma unroll
    for (int s = 16; s >= 1; s >>= 1) acc += __shfl_xor_sync(0xffffffffu, acc, s);
    if (lane == 0) g_sc[h * ENCn + e] = acc * ATT_SCALE;
}

// ---------------- cross softmax: per head over 438 -----------------------
__global__ void softmax_cross_kernel() {
    int h = blockIdx.x, tid = threadIdx.x;  // 512 threads
    __shared__ float red[512];
    float v = (tid < ENCn) ? g_sc[h * ENCn + tid] : -1e30f;
    red[tid] = v;
    __syncthreads();
    #pragma unroll
    for (int s = 256; s >= 1; s >>= 1) {
        if (tid < s) red[tid] = fmaxf(red[tid], red[tid + s]);
        __syncthreads();
    }
    float m = red[0];
    __syncthreads();
    float e = (tid < ENCn) ? expf(v - m) : 0.0f;
    red[tid] = e;
    __syncthreads();
    #pragma unroll
    for (int s = 256; s >= 1; s >>= 1) {
        if (tid < s) red[tid] += red[tid + s];
        __syncthreads();
    }
    float inv = 1.0f / red[0];
    if (tid < ENCn) g_a[h * ENCn + tid] = e * inv;
}

// ---------------- u[h][d] = sum_e a[h][e] * E[e][d] ----------------------
// grid = 8 (per head), block = 1024 (d)
__global__ void u_kernel(const float* __restrict__ E) {
    int h = blockIdx.x, d = threadIdx.x;
    __shared__ float a[ENCn];
    if (d < ENCn) a[d] = g_a[h * ENCn + d];
    __syncthreads();
    float acc0 = 0.0f, acc1 = 0.0f;
    int e = 0;
    #pragma unroll 2
    for (; e + 1 < ENCn; e += 2) {
        acc0 += a[e] * E[(size_t)e * Dm + d];
        acc1 += a[e + 1] * E[(size_t)(e + 1) * Dm + d];
    }
    if (e < ENCn) acc0 += a[e] * E[(size_t)e * Dm + d];
    g_u[h * Dm + d] = acc0 + acc1;
}

// ---------------- final LN + tied lm_head --------------------------------
// grid = 2048, block = 256 (8 warps, warp per vocab row)
__global__ void lm_head_kernel(const float* __restrict__ emb,
                               const float* __restrict__ gamma,
                               const float* __restrict__ beta,
                               float* __restrict__ out) {
    __shared__ float hx[Dm];
    __shared__ float red[256];
    int tid = threadIdx.x;
    float v[4];
    float s = 0.0f;
    #pragma unroll
    for (int r = 0; r < 4; r++) { v[r] = g_x[tid + r * 256]; s += v[r]; }
    red[tid] = s;
    __syncthreads();
    #pragma unroll
    for (int st = 128; st >= 1; st >>= 1) {
        if (tid < st) red[tid] += red[tid + st];
        __syncthreads();
    }
    float mean = red[0] * (1.0f / 1024.0f);
    __syncthreads();
    s = 0.0f;
    #pragma unroll
    for (int r = 0; r < 4; r++) { v[r] -= mean; s += v[r] * v[r]; }
    red[tid] = s;
    __syncthreads();
    #pragma unroll
    for (int st = 128; st >= 1; st >>= 1) {
        if (tid < st) red[tid] += red[tid + st];
        __syncthreads();
    }
    float inv = rsqrtf(red[0] * (1.0f / 1024.0f) + 1e-5f);
    __syncthreads();
    #pragma unroll
    for (int r = 0; r < 4; r++)
        hx[tid + r * 256] = v[r] * inv * gamma[tid + r * 256] + beta[tid + r * 256];
    __syncthreads();

    int gw = blockIdx.x * 8 + (tid >> 5);
    int lane = tid & 31;
    const float* erow = emb + (size_t)gw * Dm;
    float acc = 0.0f;
    #pragma unroll
    for (int r = 0; r < 8; r++) {
        int i = r * 128 + lane * 4;
        float4 e4 = *(const float4*)(erow + i);
        acc += e4.x * hx[i] + e4.y * hx[i + 1] + e4.z * hx[i + 2] + e4.w * hx[i + 3];
    }
    #pragma unroll
    for (int st = 16; st >= 1; st >>= 1) acc += __shfl_xor_sync(0xffffffffu, acc, st);
    if (lane == 0) out[gw] = acc;
}

// ---------------- launch ----------------
extern "C" void kernel_launch(void* const* d_in, const int* in_sizes, int n_in,
                              void* d_out, int out_size) {
    const int*   ids    = (const int*)d_in[0];
    const float* enc    = (const float*)d_in[1];
    const float* past_k = (const float*)d_in[2];
    const float* past_v = (const float*)d_in[3];
    const float* emb    = (const float*)d_in[4];
    const float* pos    = (const float*)d_in[5];
    const float* ln1_g  = (const float*)d_in[6];
    const float* ln1_b  = (const float*)d_in[7];
    const float* wq_s   = (const float*)d_in[8];
    const float* wk_s   = (const float*)d_in[9];
    const float* wv_s   = (const float*)d_in[10];
    const float* wo_s   = (const float*)d_in[11];
    const float* ln2_g  = (const float*)d_in[12];
    const float* ln2_b  = (const float*)d_in[13];
    const float* wq_c   = (const float*)d_in[14];
    const float* wk_c   = (const float*)d_in[15];
    const float* wv_c   = (const float*)d_in[16];
    const float* wo_c   = (const float*)d_in[17];
    const float* ln3_g  = (const float*)d_in[18];
    const float* ln3_b  = (const float*)d_in[19];
    const float* w1     = (const float*)d_in[20];
    const float* w2     = (const float*)d_in[21];
    const float* lnf_g  = (const float*)d_in[22];
    const float* lnf_b  = (const float*)d_in[23];
    float* out = (float*)d_out;

    float *px, *patto, *pqc, *pu, *pffn;
    cudaGetSymbolAddress((void**)&px,    g_x);
    cudaGetSymbolAddress((void**)&patto, g_att_o);
    cudaGetSymbolAddress((void**)&pqc,   g_qc);
    cudaGetSymbolAddress((void**)&pu,    g_u);
    cudaGetSymbolAddress((void**)&pffn,  g_ffn);

    const size_t DD = (size_t)Dm * Dm;
    const size_t KVL = (size_t)Hn * PASTn * DHn;

    embed_kernel<<<1, Dm>>>(ids, emb, pos);

    for (int l = 0; l < Lnum; l++) {
        // --- self attention ---
        qkv3_kernel<<<384, 1024>>>(wq_s + l * DD, wk_s + l * DD, wv_s + l * DD,
                                   ln1_g + l * Dm, ln1_b + l * Dm);
        self_attn_kernel<<<8, 1024>>>(past_k + l * KVL, past_v + l * KVL);
        matvec_kernel<1024, false, false, true, false><<<128, 1024>>>(
            wo_s + l * DD, patto, nullptr, nullptr, px, Dm);
        // --- cross attention (algebraically restructured) ---
        matvec_kernel<1024, true, false, false, false><<<128, 1024>>>(
            wq_c + l * DD, px, ln2_g + l * Dm, ln2_b + l * Dm, pqc, Dm);
        t_kernel<<<1024, 256>>>(wk_c + l * DD);
        scores_kernel<<<438, 256>>>(enc);
        softmax_cross_kernel<<<8, 512>>>();
        u_kernel<<<8, 1024>>>(enc);
        matvec_kernel<1024, false, false, false, true><<<128, 1024>>>(
            wv_c + l * DD, pu, nullptr, nullptr, patto, Dm);
        matvec_kernel<1024, false, false, true, false><<<128, 1024>>>(
            wo_c + l * DD, patto, nullptr, nullptr, px, Dm);
        // --- FFN ---
        matvec_kernel<1024, true, true, false, false><<<512, 1024>>>(
            w1 + (size_t)l * Dm * Fn, px, ln3_g + l * Dm, ln3_b + l * Dm, pffn, Fn);
        matvec_kernel<4096, false, false, true, false><<<128, 1024>>>(
            w2 + (size_t)l * Fn * Dm, pffn, nullptr, nullptr, px, Dm);
    }

    lm_head_kernel<<<2048, 256>>>(emb, lnf_g, lnf_b, out);
}

// round 2
// speedup vs baseline: 1.2485x; 1.2485x over previous
#include <cuda_runtime.h>
#include <cstdint>
#include <math.h>

#define Dm 1024
#define Hn 8
#define DHn 128
#define Fn 4096
#define Vn 16384
#define ENCn 438
#define PASTn 447
#define TOTn 448
#define Lnum 8
#define NSPLIT 14
#define ATT_SCALE 0.08838834764831845f

// ---------------- device scratch ----------------
__device__ float g_x[Dm];
__device__ float g_qkv[3 * Dm];
__device__ float g_att_o[Dm];
__device__ float g_qc[Dm];
__device__ float g_t[Hn * Dm];
__device__ float g_sc[Hn * ENCn];
__device__ float g_a[Hn * ENCn];
__device__ float g_u[Hn * Dm];
__device__ float g_ffn[Fn];
__device__ float g_po[Hn * NSPLIT * DHn];
__device__ float g_pm[Hn * NSPLIT];
__device__ float g_ps[Hn * NSPLIT];

__device__ __forceinline__ float gelu_f(float v) {
    float c = v * v * v;
    return 0.5f * v * (1.0f + tanhf(0.7978845608028654f * (v + 0.044715f * c)));
}

// ---------------- embedding ----------------
__global__ void embed_kernel(const int* __restrict__ ids,
                             const float* __restrict__ emb,
                             const float* __restrict__ pos) {
    int t = threadIdx.x;  // 256
    int id = ids[0];
    const float4* e4 = (const float4*)(emb + (size_t)id * Dm);
    const float4* p4 = (const float4*)(pos + (size_t)PASTn * Dm);
    float4 a = e4[t], b = p4[t];
    a.x += b.x; a.y += b.y; a.z += b.z; a.w += b.w;
    ((float4*)g_x)[t] = a;
}

// ---------------- generic column matvec ----------------
// out[j] = sum_i x[i] * W[i*dout + j], one float4 output quad per block.
// Block = 256 threads; thread t accumulates rows i = t, t+256, ...
// grid.x = dout/4, grid.y = multi (W select / head / output slice)
template <bool LN, bool GELU, bool RES, bool PERHEAD>
__global__ void mv2(const float* __restrict__ Wa,
                    const float* __restrict__ Wb,
                    const float* __restrict__ Wc,
                    const float* __restrict__ xin,
                    const float* __restrict__ gamma,
                    const float* __restrict__ beta,
                    float* __restrict__ out,
                    int din, int dout4, int xstride, int ostride) {
    __shared__ float sx[4096];
    __shared__ float4 sred[8];
    int tid = threadIdx.x;
    int wid = tid >> 5, lane = tid & 31;
    int y = blockIdx.y;

    const float* W = (y == 0) ? Wa : ((y == 1) ? Wb : Wc);
    const float* xe = xin + (size_t)y * xstride;
    if (PERHEAD) xe += ((blockIdx.x >> 5) << 10);  // head = (blockIdx.x*4)>>7

    if (LN) {  // din == 1024
        __shared__ float wred[8];
        float4 xv = ((const float4*)xe)[tid];
        float s = xv.x + xv.y + xv.z + xv.w;
        #pragma unroll
        for (int m = 16; m >= 1; m >>= 1) s += __shfl_xor_sync(0xffffffffu, s, m);
        if (lane == 0) wred[wid] = s;
        __syncthreads();
        float mean = 0.0f;
        #pragma unroll
        for (int i = 0; i < 8; i++) mean += wred[i];
        mean *= (1.0f / 1024.0f);
        float4 dv;
        dv.x = xv.x - mean; dv.y = xv.y - mean; dv.z = xv.z - mean; dv.w = xv.w - mean;
        float s2 = dv.x * dv.x + dv.y * dv.y + dv.z * dv.z + dv.w * dv.w;
        #pragma unroll
        for (int m = 16; m >= 1; m >>= 1) s2 += __shfl_xor_sync(0xffffffffu, s2, m);
        __syncthreads();
        if (lane == 0) wred[wid] = s2;
        __syncthreads();
        float var = 0.0f;
        #pragma unroll
        for (int i = 0; i < 8; i++) var += wred[i];
        float rstd = rsqrtf(var * (1.0f / 1024.0f) + 1e-5f);
        float4 g4 = ((const float4*)gamma)[tid];
        float4 b4 = ((const float4*)beta)[tid];
        float4 o;
        o.x = dv.x * rstd * g4.x + b4.x;
        o.y = dv.y * rstd * g4.y + b4.y;
        o.z = dv.z * rstd * g4.z + b4.z;
        o.w = dv.w * rstd * g4.w + b4.w;
        ((float4*)sx)[tid] = o;
        __syncthreads();
    } else {
        if ((din & 3) == 0) {
            int d4 = din >> 2;
            for (int i = tid; i < d4; i += 256) ((float4*)sx)[i] = ((const float4*)xe)[i];
        } else {
            for (int i = tid; i < din; i += 256) sx[i] = xe[i];
        }
        __syncthreads();
    }

    int j4 = blockIdx.x;
    const float4* W4 = (const float4*)W;
    float4 acc = make_float4(0.f, 0.f, 0.f, 0.f);
    #pragma unroll 4
    for (int i = tid; i < din; i += 256) {
        float xv = sx[i];
        float4 w = W4[(size_t)i * dout4 + j4];
        acc.x += xv * w.x; acc.y += xv * w.y; acc.z += xv * w.z; acc.w += xv * w.w;
    }
    #pragma unroll
    for (int m = 16; m >= 1; m >>= 1) {
        acc.x += __shfl_xor_sync(0xffffffffu, acc.x, m);
        acc.y += __shfl_xor_sync(0xffffffffu, acc.y, m);
        acc.z += __shfl_xor_sync(0xffffffffu, acc.z, m);
        acc.w += __shfl_xor_sync(0xffffffffu, acc.w, m);
    }
    if (lane == 0) sred[wid] = acc;
    __syncthreads();
    if (wid == 0) {
        float4 a = (lane < 8) ? sred[lane] : make_float4(0.f, 0.f, 0.f, 0.f);
        #pragma unroll
        for (int m = 1; m <= 4; m <<= 1) {
            a.x += __shfl_xor_sync(0xffffffffu, a.x, m);
            a.y += __shfl_xor_sync(0xffffffffu, a.y, m);
            a.z += __shfl_xor_sync(0xffffffffu, a.z, m);
            a.w += __shfl_xor_sync(0xffffffffu, a.w, m);
        }
        if (lane == 0) {
            if (GELU) {
                a.x = gelu_f(a.x); a.y = gelu_f(a.y); a.z = gelu_f(a.z); a.w = gelu_f(a.w);
            }
            float4* o4 = (float4*)(out + (size_t)y * ostride);
            if (RES) {
                float4 r = o4[j4];
                a.x += r.x; a.y += r.y; a.z += r.z; a.w += r.w;
            }
            o4[j4] = a;
        }
    }
}

// ---------------- self attention: split-KV flash, grid (NSPLIT, Hn) -------
__global__ void attnA(const float* __restrict__ past_k,
                      const float* __restrict__ past_v) {
    int split = blockIdx.x, h = blockIdx.y;
    int base = split * 32;
    int tid = threadIdx.x;  // 256
    int warp = tid >> 5, lane = tid & 31;
    __shared__ float q[DHn];
    __shared__ float sc[32];
    __shared__ float red[256];
    __shared__ float ms[2];
    if (tid < DHn) q[tid] = g_qkv[h * DHn + tid];
    __syncthreads();

    #pragma unroll
    for (int r = 0; r < 4; r++) {
        int p = base + warp * 4 + r;
        const float* krow = (p < PASTn) ? past_k + ((size_t)h * PASTn + p) * DHn
                                        : g_qkv + Dm + h * DHn;
        float4 k4 = ((const float4*)krow)[lane];
        float4 q4 = ((const float4*)q)[lane];
        float d = k4.x * q4.x + k4.y * q4.y + k4.z * q4.z + k4.w * q4.w;
        #pragma unroll
        for (int m = 16; m >= 1; m >>= 1) d += __shfl_xor_sync(0xffffffffu, d, m);
        if (lane == 0) sc[warp * 4 + r] = d * ATT_SCALE;
    }
    __syncthreads();

    if (warp == 0) {
        float v = sc[lane];
        float mloc = v;
        #pragma unroll
        for (int m = 16; m >= 1; m >>= 1)
            mloc = fmaxf(mloc, __shfl_xor_sync(0xffffffffu, mloc, m));
        float e = expf(v - mloc);
        float s = e;
        #pragma unroll
        for (int m = 16; m >= 1; m >>= 1) s += __shfl_xor_sync(0xffffffffu, s, m);
        sc[lane] = e;
        if (lane == 0) { ms[0] = mloc; ms[1] = s; }
    }
    __syncthreads();

    int c = tid & 127, pg = tid >> 7;
    float acc = 0.0f;
    #pragma unroll 4
    for (int pp = pg * 16; pp < pg * 16 + 16; pp++) {
        int p = base + pp;
        const float* vrow = (p < PASTn) ? past_v + ((size_t)h * PASTn + p) * DHn
                                        : g_qkv + 2 * Dm + h * DHn;
        acc += sc[pp] * vrow[c];
    }
    red[tid] = acc;
    __syncthreads();
    if (pg == 0) {
        g_po[(h * NSPLIT + split) * DHn + c] = red[c] + red[c + 128];
        if (c == 0) { g_pm[h * NSPLIT + split] = ms[0]; g_ps[h * NSPLIT + split] = ms[1]; }
    }
}

__global__ void attnB() {
    int h = blockIdx.x, c = threadIdx.x;  // 128
    float M = -1e30f;
    #pragma unroll
    for (int i = 0; i < NSPLIT; i++) M = fmaxf(M, g_pm[h * NSPLIT + i]);
    float S = 0.0f, o = 0.0f;
    #pragma unroll
    for (int i = 0; i < NSPLIT; i++) {
        float w = expf(g_pm[h * NSPLIT + i] - M);
        S += g_ps[h * NSPLIT + i] * w;
        o += g_po[(h * NSPLIT + i) * DHn + c] * w;
    }
    g_att_o[h * DHn + c] = o / S;
}

// ---------------- t[h][d] = q_h . wk_c[d, h*128:+128] ---------------------
// warp per output; grid 1024 x 256 threads
__global__ void t_kernel(const float* __restrict__ wk) {
    int gw = blockIdx.x * 8 + (threadIdx.x >> 5);
    int lane = threadIdx.x & 31;
    int h = gw >> 10, d = gw & 1023;
    float4 w4 = *(const float4*)(wk + (size_t)d * Dm + h * DHn + lane * 4);
    float4 q4 = *(const float4*)(g_qc + h * DHn + lane * 4);
    float acc = w4.x * q4.x + w4.y * q4.y + w4.z * q4.z + w4.w * q4.w;
    #pragma unroll
    for (int s = 16; s >= 1; s >>= 1) acc += __shfl_xor_sync(0xffffffffu, acc, s);
    if (lane == 0) g_t[gw] = acc;
}

// ---------------- scores: warp per encoder row, 8 heads per warp ---------
// grid = 55 blocks x 256 threads; E read once, t in smem
__global__ void scores2(const float* __restrict__ E) {
    __shared__ float st[Hn * Dm];
    int tid = threadIdx.x;
    for (int i = tid; i < Hn * Dm / 4; i += 256)
        ((float4*)st)[i] = ((const float4*)g_t)[i];
    __syncthreads();
    int e = blockIdx.x * 8 + (tid >> 5);
    int lane = tid & 31;
    if (e >= ENCn) return;
    const float4* erow = (const float4*)(E + (size_t)e * Dm);
    float acc[Hn];
    #pragma unroll
    for (int h = 0; h < Hn; h++) acc[h] = 0.0f;
    #pragma unroll
    for (int r = 0; r < 8; r++) {
        float4 e4 = erow[r * 32 + lane];
        #pragma unroll
        for (int h = 0; h < Hn; h++) {
            float4 t4 = ((const float4*)(st + h * Dm))[r * 32 + lane];
            acc[h] += e4.x * t4.x + e4.y * t4.y + e4.z * t4.z + e4.w * t4.w;
        }
    }
    #pragma unroll
    for (int h = 0; h < Hn; h++) {
        #pragma unroll
        for (int m = 16; m >= 1; m >>= 1)
            acc[h] += __shfl_xor_sync(0xffffffffu, acc[h], m);
    }
    if (lane == 0) {
        #pragma unroll
        for (int h = 0; h < Hn; h++) g_sc[h * ENCn + e] = acc[h] * ATT_SCALE;
    }
}

// ---------------- cross softmax ----------------
__global__ void softmax_cross_kernel() {
    int h = blockIdx.x, tid = threadIdx.x;  // 512
    __shared__ float red[512];
    float v = (tid < ENCn) ? g_sc[h * ENCn + tid] : -1e30f;
    red[tid] = v;
    __syncthreads();
    #pragma unroll
    for (int s = 256; s >= 1; s >>= 1) {
        if (tid < s) red[tid] = fmaxf(red[tid], red[tid + s]);
        __syncthreads();
    }
    float m = red[0];
    __syncthreads();
    float e = (tid < ENCn) ? expf(v - m) : 0.0f;
    red[tid] = e;
    __syncthreads();
    #pragma unroll
    for (int s = 256; s >= 1; s >>= 1) {
        if (tid < s) red[tid] += red[tid + s];
        __syncthreads();
    }
    float inv = 1.0f / red[0];
    if (tid < ENCn) g_a[h * ENCn + tid] = e * inv;
}

// ---------------- final LN + tied lm_head --------------------------------
__global__ void lm_head_kernel(const float* __restrict__ emb,
                               const float* __restrict__ gamma,
                               const float* __restrict__ beta,
                               float* __restrict__ out) {
    __shared__ float hx[Dm];
    __shared__ float red[256];
    int tid = threadIdx.x;
    float v[4];
    float s = 0.0f;
    #pragma unroll
    for (int r = 0; r < 4; r++) { v[r] = g_x[tid + r * 256]; s += v[r]; }
    red[tid] = s;
    __syncthreads();
    #pragma unroll
    for (int st = 128; st >= 1; st >>= 1) {
        if (tid < st) red[tid] += red[tid + st];
        __syncthreads();
    }
    float mean = red[0] * (1.0f / 1024.0f);
    __syncthreads();
    s = 0.0f;
    #pragma unroll
    for (int r = 0; r < 4; r++) { v[r] -= mean; s += v[r] * v[r]; }
    red[tid] = s;
    __syncthreads();
    #pragma unroll
    for (int st = 128; st >= 1; st >>= 1) {
        if (tid < st) red[tid] += red[tid + st];
        __syncthreads();
    }
    float inv = rsqrtf(red[0] * (1.0f / 1024.0f) + 1e-5f);
    __syncthreads();
    #pragma unroll
    for (int r = 0; r < 4; r++)
        hx[tid + r * 256] = v[r] * inv * gamma[tid + r * 256] + beta[tid + r * 256];
    __syncthreads();

    int gw = blockIdx.x * 8 + (tid >> 5);
    int lane = tid & 31;
    const float4* erow = (const float4*)(emb + (size_t)gw * Dm);
    const float4* hx4 = (const float4*)hx;
    float acc = 0.0f;
    #pragma unroll
    for (int r = 0; r < 8; r++) {
        float4 e4 = erow[r * 32 + lane];
        float4 h4 = hx4[r * 32 + lane];
        acc += e4.x * h4.x + e4.y * h4.y + e4.z * h4.z + e4.w * h4.w;
    }
    #pragma unroll
    for (int st = 16; st >= 1; st >>= 1) acc += __shfl_xor_sync(0xffffffffu, acc, st);
    if (lane == 0) out[gw] = acc;
}

// ---------------- launch ----------------
extern "C" void kernel_launch(void* const* d_in, const int* in_sizes, int n_in,
                              void* d_out, int out_size) {
    const int*   ids    = (const int*)d_in[0];
    const float* enc    = (const float*)d_in[1];
    const float* past_k = (const float*)d_in[2];
    const float* past_v = (const float*)d_in[3];
    const float* emb    = (const float*)d_in[4];
    const float* pos    = (const float*)d_in[5];
    const float* ln1_g  = (const float*)d_in[6];
    const float* ln1_b  = (const float*)d_in[7];
    const float* wq_s   = (const float*)d_in[8];
    const float* wk_s   = (const float*)d_in[9];
    const float* wv_s   = (const float*)d_in[10];
    const float* wo_s   = (const float*)d_in[11];
    const float* ln2_g  = (const float*)d_in[12];
    const float* ln2_b  = (const float*)d_in[13];
    const float* wq_c   = (const float*)d_in[14];
    const float* wk_c   = (const float*)d_in[15];
    const float* wv_c   = (const float*)d_in[16];
    const float* wo_c   = (const float*)d_in[17];
    const float* ln3_g  = (const float*)d_in[18];
    const float* ln3_b  = (const float*)d_in[19];
    const float* w1     = (const float*)d_in[20];
    const float* w2     = (const float*)d_in[21];
    const float* lnf_g  = (const float*)d_in[22];
    const float* lnf_b  = (const float*)d_in[23];
    float* out = (float*)d_out;

    float *px, *pqkv, *patto, *pqc, *pa, *pu, *pffn;
    cudaGetSymbolAddress((void**)&px,    g_x);
    cudaGetSymbolAddress((void**)&pqkv,  g_qkv);
    cudaGetSymbolAddress((void**)&patto, g_att_o);
    cudaGetSymbolAddress((void**)&pqc,   g_qc);
    cudaGetSymbolAddress((void**)&pa,    g_a);
    cudaGetSymbolAddress((void**)&pu,    g_u);
    cudaGetSymbolAddress((void**)&pffn,  g_ffn);

    const size_t DD = (size_t)Dm * Dm;
    const size_t KVL = (size_t)Hn * PASTn * DHn;

    embed_kernel<<<1, 256>>>(ids, emb, pos);

    for (int l = 0; l < Lnum; l++) {
        // --- self attention ---
        mv2<true, false, false, false><<<dim3(256, 3), 256>>>(
            wq_s + l * DD, wk_s + l * DD, wv_s + l * DD,
            px, ln1_g + l * Dm, ln1_b + l * Dm, pqkv, Dm, 256, 0, Dm);
        attnA<<<dim3(NSPLIT, Hn), 256>>>(past_k + l * KVL, past_v + l * KVL);
        attnB<<<Hn, 128>>>();
        mv2<false, false, true, false><<<256, 256>>>(
            wo_s + l * DD, nullptr, nullptr, patto, nullptr, nullptr, px, Dm, 256, 0, 0);
        // --- cross attention (restructured) ---
        mv2<true, false, false, false><<<256, 256>>>(
            wq_c + l * DD, nullptr, nullptr, px, ln2_g + l * Dm, ln2_b + l * Dm,
            pqc, Dm, 256, 0, 0);
        t_kernel<<<1024, 256>>>(wk_c + l * DD);
        scores2<<<55, 256>>>(enc);
        softmax_cross_kernel<<<Hn, 512>>>();
        mv2<false, false, false, false><<<dim3(256, Hn), 256>>>(
            enc, enc, enc, pa, nullptr, nullptr, pu, ENCn, 256, ENCn, Dm);
        mv2<false, false, false, true><<<256, 256>>>(
            wv_c + l * DD, nullptr, nullptr, pu, nullptr, nullptr, patto, Dm, 256, 0, 0);
        mv2<false, false, true, false><<<256, 256>>>(
            wo_c + l * DD, nullptr, nullptr, patto, nullptr, nullptr, px, Dm, 256, 0, 0);
        // --- FFN ---
        mv2<true, true, false, false><<<1024, 256>>>(
            w1 + (size_t)l * Dm * Fn, nullptr, nullptr, px, ln3_g + l * Dm, ln3_b + l * Dm,
            pffn, Dm, 1024, 0, 0);
        mv2<false, false, true, false><<<256, 256>>>(
            w2 + (size_t)l * Fn * Dm, nullptr, nullptr, pffn, nullptr, nullptr,
            px, Fn, 256, 0, 0);
    }

    lm_head_kernel<<<2048, 256>>>(emb, lnf_g, lnf_b, out);
}

// round 3
// speedup vs baseline: 1.2627x; 1.0113x over previous
#include <cuda_runtime.h>
#include <cstdint>
#include <math.h>

#define Dm 1024
#define Hn 8
#define DHn 128
#define Fn 4096
#define Vn 16384
#define ENCn 438
#define PASTn 447
#define TOTn 448
#define Lnum 8
#define NSPLIT 14
#define ATT_SCALE 0.08838834764831845f

// ---------------- device scratch ----------------
__device__ float g_x[Dm];
__device__ float g_qkv[3 * Dm];
__device__ float g_att_o[Dm];
__device__ float g_qc[Dm];
__device__ float g_t[Hn * Dm];
__device__ float g_sc[Hn * ENCn];
__device__ float g_u[Hn * Dm];
__device__ float g_ffn[Fn];
__device__ float g_po[Hn * NSPLIT * DHn];
__device__ float g_pm[Hn * NSPLIT];
__device__ float g_ps[Hn * NSPLIT];

__device__ __forceinline__ float gelu_f(float v) {
    float c = v * v * v;
    return 0.5f * v * (1.0f + tanhf(0.7978845608028654f * (v + 0.044715f * c)));
}

// ---------------- embedding ----------------
__global__ void embed_kernel(const int* __restrict__ ids,
                             const float* __restrict__ emb,
                             const float* __restrict__ pos) {
    int t = threadIdx.x;  // 256
    int id = ids[0];
    const float4* e4 = (const float4*)(emb + (size_t)id * Dm);
    const float4* p4 = (const float4*)(pos + (size_t)PASTn * Dm);
    float4 a = e4[t], b = p4[t];
    a.x += b.x; a.y += b.y; a.z += b.z; a.w += b.w;
    ((float4*)g_x)[t] = a;
}

// ---------------- generic column matvec ----------------
// out[j] = sum_i sx[i] * W[i*dout + j]; one float4 output quad per block.
// sx filled from: COMBINE (split-KV attention partials), SOFTM (softmax of
// scores), LN (layernorm of xin), or raw copy of xin.
template <bool LN, bool GELU, bool RES, bool PERHEAD, bool COMBINE, bool SOFTM>
__global__ void mv2(const float* __restrict__ Wa,
                    const float* __restrict__ Wb,
                    const float* __restrict__ Wc,
                    const float* __restrict__ xin,
                    const float* __restrict__ gamma,
                    const float* __restrict__ beta,
                    float* __restrict__ out,
                    int din, int dout4, int xstride, int ostride) {
    __shared__ float sx[4096];
    __shared__ float4 sred[8];
    __shared__ float wred[8];
    int tid = threadIdx.x;
    int wid = tid >> 5, lane = tid & 31;
    int y = blockIdx.y;

    const float* W = (y == 0) ? Wa : ((y == 1) ? Wb : Wc);
    const float* xe = xin + (size_t)y * xstride;
    if (PERHEAD) xe += ((blockIdx.x >> 5) << 10);

    if (COMBINE) {
        // reconstruct attention output from split-KV partials
        __shared__ float spm[Hn * NSPLIT];
        __shared__ float sps[Hn * NSPLIT];
        if (tid < Hn * NSPLIT) { spm[tid] = g_pm[tid]; sps[tid] = g_ps[tid]; }
        __syncthreads();
        #pragma unroll
        for (int r = 0; r < 4; r++) {
            int i = r * 256 + tid;
            int h = i >> 7, c = i & 127;
            float M = -1e30f;
            #pragma unroll
            for (int s = 0; s < NSPLIT; s++) M = fmaxf(M, spm[h * NSPLIT + s]);
            float S = 0.0f, o = 0.0f;
            #pragma unroll
            for (int s = 0; s < NSPLIT; s++) {
                float w = expf(spm[h * NSPLIT + s] - M);
                S += sps[h * NSPLIT + s] * w;
                o += g_po[(h * NSPLIT + s) * DHn + c] * w;
            }
            sx[i] = o / S;
        }
        __syncthreads();
    } else if (SOFTM) {
        // din == ENCn(438): softmax of raw scores for head y
        float v0 = xe[tid];
        float v1 = (tid + 256 < ENCn) ? xe[tid + 256] : -1e30f;
        float m = fmaxf(v0, v1);
        #pragma unroll
        for (int s = 16; s >= 1; s >>= 1) m = fmaxf(m, __shfl_xor_sync(0xffffffffu, m, s));
        if (lane == 0) wred[wid] = m;
        __syncthreads();
        float M = wred[0];
        #pragma unroll
        for (int i = 1; i < 8; i++) M = fmaxf(M, wred[i]);
        float e0 = expf(v0 - M);
        float e1 = (tid + 256 < ENCn) ? expf(v1 - M) : 0.0f;
        float s = e0 + e1;
        #pragma unroll
        for (int mm = 16; mm >= 1; mm >>= 1) s += __shfl_xor_sync(0xffffffffu, s, mm);
        __syncthreads();
        if (lane == 0) wred[wid] = s;
        __syncthreads();
        float S = 0.0f;
        #pragma unroll
        for (int i = 0; i < 8; i++) S += wred[i];
        float inv = 1.0f / S;
        sx[tid] = e0 * inv;
        if (tid + 256 < ENCn) sx[tid + 256] = e1 * inv;
        __syncthreads();
    } else if (LN) {
        float4 xv = ((const float4*)xe)[tid];
        float s = xv.x + xv.y + xv.z + xv.w;
        #pragma unroll
        for (int m = 16; m >= 1; m >>= 1) s += __shfl_xor_sync(0xffffffffu, s, m);
        if (lane == 0) wred[wid] = s;
        __syncthreads();
        float mean = 0.0f;
        #pragma unroll
        for (int i = 0; i < 8; i++) mean += wred[i];
        mean *= (1.0f / 1024.0f);
        float4 dv;
        dv.x = xv.x - mean; dv.y = xv.y - mean; dv.z = xv.z - mean; dv.w = xv.w - mean;
        float s2 = dv.x * dv.x + dv.y * dv.y + dv.z * dv.z + dv.w * dv.w;
        #pragma unroll
        for (int m = 16; m >= 1; m >>= 1) s2 += __shfl_xor_sync(0xffffffffu, s2, m);
        __syncthreads();
        if (lane == 0) wred[wid] = s2;
        __syncthreads();
        float var = 0.0f;
        #pragma unroll
        for (int i = 0; i < 8; i++) var += wred[i];
        float rstd = rsqrtf(var * (1.0f / 1024.0f) + 1e-5f);
        float4 g4 = ((const float4*)gamma)[tid];
        float4 b4 = ((const float4*)beta)[tid];
        float4 o;
        o.x = dv.x * rstd * g4.x + b4.x;
        o.y = dv.y * rstd * g4.y + b4.y;
        o.z = dv.z * rstd * g4.z + b4.z;
        o.w = dv.w * rstd * g4.w + b4.w;
        ((float4*)sx)[tid] = o;
        __syncthreads();
    } else {
        if ((din & 3) == 0) {
            int d4 = din >> 2;
            for (int i = tid; i < d4; i += 256) ((float4*)sx)[i] = ((const float4*)xe)[i];
        } else {
            for (int i = tid; i < din; i += 256) sx[i] = xe[i];
        }
        __syncthreads();
    }

    int j4 = blockIdx.x;
    const float4* W4 = (const float4*)W;
    float4 acc = make_float4(0.f, 0.f, 0.f, 0.f);
    #pragma unroll 4
    for (int i = tid; i < din; i += 256) {
        float xv = sx[i];
        float4 w = W4[(size_t)i * dout4 + j4];
        acc.x += xv * w.x; acc.y += xv * w.y; acc.z += xv * w.z; acc.w += xv * w.w;
    }
    #pragma unroll
    for (int m = 16; m >= 1; m >>= 1) {
        acc.x += __shfl_xor_sync(0xffffffffu, acc.x, m);
        acc.y += __shfl_xor_sync(0xffffffffu, acc.y, m);
        acc.z += __shfl_xor_sync(0xffffffffu, acc.z, m);
        acc.w += __shfl_xor_sync(0xffffffffu, acc.w, m);
    }
    if (lane == 0) sred[wid] = acc;
    __syncthreads();
    if (wid == 0) {
        float4 a = (lane < 8) ? sred[lane] : make_float4(0.f, 0.f, 0.f, 0.f);
        #pragma unroll
        for (int m = 1; m <= 4; m <<= 1) {
            a.x += __shfl_xor_sync(0xffffffffu, a.x, m);
            a.y += __shfl_xor_sync(0xffffffffu, a.y, m);
            a.z += __shfl_xor_sync(0xffffffffu, a.z, m);
            a.w += __shfl_xor_sync(0xffffffffu, a.w, m);
        }
        if (lane == 0) {
            if (GELU) {
                a.x = gelu_f(a.x); a.y = gelu_f(a.y); a.z = gelu_f(a.z); a.w = gelu_f(a.w);
            }
            float4* o4 = (float4*)(out + (size_t)y * ostride);
            if (RES) {
                float4 r = o4[j4];
                a.x += r.x; a.y += r.y; a.z += r.z; a.w += r.w;
            }
            o4[j4] = a;
        }
    }
}

// ---------------- self attention: split-KV flash, grid (NSPLIT, Hn) -------
__global__ void attnA(const float* __restrict__ past_k,
                      const float* __restrict__ past_v) {
    int split = blockIdx.x, h = blockIdx.y;
    int base = split * 32;
    int tid = threadIdx.x;  // 256
    int warp = tid >> 5, lane = tid & 31;
    __shared__ float q[DHn];
    __shared__ float sc[32];
    __shared__ float red[256];
    __shared__ float ms[2];
    if (tid < DHn) q[tid] = g_qkv[h * DHn + tid];
    __syncthreads();

    #pragma unroll
    for (int r = 0; r < 4; r++) {
        int p = base + warp * 4 + r;
        const float* krow = (p < PASTn) ? past_k + ((size_t)h * PASTn + p) * DHn
                                        : g_qkv + Dm + h * DHn;
        float4 k4 = ((const float4*)krow)[lane];
        float4 q4 = ((const float4*)q)[lane];
        float d = k4.x * q4.x + k4.y * q4.y + k4.z * q4.z + k4.w * q4.w;
        #pragma unroll
        for (int m = 16; m >= 1; m >>= 1) d += __shfl_xor_sync(0xffffffffu, d, m);
        if (lane == 0) sc[warp * 4 + r] = d * ATT_SCALE;
    }
    __syncthreads();

    if (warp == 0) {
        float v = sc[lane];
        float mloc = v;
        #pragma unroll
        for (int m = 16; m >= 1; m >>= 1)
            mloc = fmaxf(mloc, __shfl_xor_sync(0xffffffffu, mloc, m));
        float e = expf(v - mloc);
        float s = e;
        #pragma unroll
        for (int m = 16; m >= 1; m >>= 1) s += __shfl_xor_sync(0xffffffffu, s, m);
        sc[lane] = e;
        if (lane == 0) { ms[0] = mloc; ms[1] = s; }
    }
    __syncthreads();

    int c = tid & 127, pg = tid >> 7;
    float acc = 0.0f;
    #pragma unroll 4
    for (int pp = pg * 16; pp < pg * 16 + 16; pp++) {
        int p = base + pp;
        const float* vrow = (p < PASTn) ? past_v + ((size_t)h * PASTn + p) * DHn
                                        : g_qkv + 2 * Dm + h * DHn;
        acc += sc[pp] * vrow[c];
    }
    red[tid] = acc;
    __syncthreads();
    if (pg == 0) {
        g_po[(h * NSPLIT + split) * DHn + c] = red[c] + red[c + 128];
        if (c == 0) { g_pm[h * NSPLIT + split] = ms[0]; g_ps[h * NSPLIT + split] = ms[1]; }
    }
}

// ---------------- t[h][d] = q_h . wk_c[d, h*128:+128] ---------------------
__global__ void t_kernel(const float* __restrict__ wk) {
    int gw = blockIdx.x * 8 + (threadIdx.x >> 5);
    int lane = threadIdx.x & 31;
    int h = gw >> 10, d = gw & 1023;
    float4 w4 = *(const float4*)(wk + (size_t)d * Dm + h * DHn + lane * 4);
    float4 q4 = *(const float4*)(g_qc + h * DHn + lane * 4);
    float acc = w4.x * q4.x + w4.y * q4.y + w4.z * q4.z + w4.w * q4.w;
    #pragma unroll
    for (int s = 16; s >= 1; s >>= 1) acc += __shfl_xor_sync(0xffffffffu, acc, s);
    if (lane == 0) g_t[gw] = acc;
}

// ---------------- scores: warp per encoder row, 8 heads per warp ---------
__global__ void scores2(const float* __restrict__ E) {
    __shared__ float st[Hn * Dm];
    int tid = threadIdx.x;
    for (int i = tid; i < Hn * Dm / 4; i += 256)
        ((float4*)st)[i] = ((const float4*)g_t)[i];
    __syncthreads();
    int e = blockIdx.x * 8 + (tid >> 5);
    int lane = tid & 31;
    if (e >= ENCn) return;
    const float4* erow = (const float4*)(E + (size_t)e * Dm);
    float acc[Hn];
    #pragma unroll
    for (int h = 0; h < Hn; h++) acc[h] = 0.0f;
    #pragma unroll
    for (int r = 0; r < 8; r++) {
        float4 e4 = erow[r * 32 + lane];
        #pragma unroll
        for (int h = 0; h < Hn; h++) {
            float4 t4 = ((const float4*)(st + h * Dm))[r * 32 + lane];
            acc[h] += e4.x * t4.x + e4.y * t4.y + e4.z * t4.z + e4.w * t4.w;
        }
    }
    #pragma unroll
    for (int h = 0; h < Hn; h++) {
        #pragma unroll
        for (int m = 16; m >= 1; m >>= 1)
            acc[h] += __shfl_xor_sync(0xffffffffu, acc[h], m);
    }
    if (lane == 0) {
        #pragma unroll
        for (int h = 0; h < Hn; h++) g_sc[h * ENCn + e] = acc[h] * ATT_SCALE;
    }
}

// ---------------- final LN + tied lm_head --------------------------------
__global__ void lm_head_kernel(const float* __restrict__ emb,
                               const float* __restrict__ gamma,
                               const float* __restrict__ beta,
                               float* __restrict__ out) {
    __shared__ float hx[Dm];
    __shared__ float red[256];
    int tid = threadIdx.x;
    float v[4];
    float s = 0.0f;
    #pragma unroll
    for (int r = 0; r < 4; r++) { v[r] = g_x[tid + r * 256]; s += v[r]; }
    red[tid] = s;
    __syncthreads();
    #pragma unroll
    for (int st = 128; st >= 1; st >>= 1) {
        if (tid < st) red[tid] += red[tid + st];
        __syncthreads();
    }
    float mean = red[0] * (1.0f / 1024.0f);
    __syncthreads();
    s = 0.0f;
    #pragma unroll
    for (int r = 0; r < 4; r++) { v[r] -= mean; s += v[r] * v[r]; }
    red[tid] = s;
    __syncthreads();
    #pragma unroll
    for (int st = 128; st >= 1; st >>= 1) {
        if (tid < st) red[tid] += red[tid + st];
        __syncthreads();
    }
    float inv = rsqrtf(red[0] * (1.0f / 1024.0f) + 1e-5f);
    __syncthreads();
    #pragma unroll
    for (int r = 0; r < 4; r++)
        hx[tid + r * 256] = v[r] * inv * gamma[tid + r * 256] + beta[tid + r * 256];
    __syncthreads();

    int gw = blockIdx.x * 8 + (tid >> 5);
    int lane = tid & 31;
    const float4* erow = (const float4*)(emb + (size_t)gw * Dm);
    const float4* hx4 = (const float4*)hx;
    float acc = 0.0f;
    #pragma unroll
    for (int r = 0; r < 8; r++) {
        float4 e4 = erow[r * 32 + lane];
        float4 h4 = hx4[r * 32 + lane];
        acc += e4.x * h4.x + e4.y * h4.y + e4.z * h4.z + e4.w * h4.w;
    }
    #pragma unroll
    for (int st = 16; st >= 1; st >>= 1) acc += __shfl_xor_sync(0xffffffffu, acc, st);
    if (lane == 0) out[gw] = acc;
}

// ---------------- launch ----------------
extern "C" void kernel_launch(void* const* d_in, const int* in_sizes, int n_in,
                              void* d_out, int out_size) {
    const int*   ids    = (const int*)d_in[0];
    const float* enc    = (const float*)d_in[1];
    const float* past_k = (const float*)d_in[2];
    const float* past_v = (const float*)d_in[3];
    const float* emb    = (const float*)d_in[4];
    const float* pos    = (const float*)d_in[5];
    const float* ln1_g  = (const float*)d_in[6];
    const float* ln1_b  = (const float*)d_in[7];
    const float* wq_s   = (const float*)d_in[8];
    const float* wk_s   = (const float*)d_in[9];
    const float* wv_s   = (const float*)d_in[10];
    const float* wo_s   = (const float*)d_in[11];
    const float* ln2_g  = (const float*)d_in[12];
    const float* ln2_b  = (const float*)d_in[13];
    const float* wq_c   = (const float*)d_in[14];
    const float* wk_c   = (const float*)d_in[15];
    const float* wv_c   = (const float*)d_in[16];
    const float* wo_c   = (const float*)d_in[17];
    const float* ln3_g  = (const float*)d_in[18];
    const float* ln3_b  = (const float*)d_in[19];
    const float* w1     = (const float*)d_in[20];
    const float* w2     = (const float*)d_in[21];
    const float* lnf_g  = (const float*)d_in[22];
    const float* lnf_b  = (const float*)d_in[23];
    float* out = (float*)d_out;

    float *px, *pqkv, *patto, *pqc, *psc, *pu, *pffn;
    cudaGetSymbolAddress((void**)&px,    g_x);
    cudaGetSymbolAddress((void**)&pqkv,  g_qkv);
    cudaGetSymbolAddress((void**)&patto, g_att_o);
    cudaGetSymbolAddress((void**)&pqc,   g_qc);
    cudaGetSymbolAddress((void**)&psc,   g_sc);
    cudaGetSymbolAddress((void**)&pu,    g_u);
    cudaGetSymbolAddress((void**)&pffn,  g_ffn);

    const size_t DD = (size_t)Dm * Dm;
    const size_t KVL = (size_t)Hn * PASTn * DHn;

    embed_kernel<<<1, 256>>>(ids, emb, pos);

    for (int l = 0; l < Lnum; l++) {
        // --- self attention ---
        mv2<true, false, false, false, false, false><<<dim3(256, 3), 256>>>(
            wq_s + l * DD, wk_s + l * DD, wv_s + l * DD,
            px, ln1_g + l * Dm, ln1_b + l * Dm, pqkv, Dm, 256, 0, Dm);
        attnA<<<dim3(NSPLIT, Hn), 256>>>(past_k + l * KVL, past_v + l * KVL);
        // o-proj with inline split-KV combine
        mv2<false, false, true, false, true, false><<<256, 256>>>(
            wo_s + l * DD, nullptr, nullptr, px, nullptr, nullptr, px, Dm, 256, 0, 0);
        // --- cross attention (restructured) ---
        mv2<true, false, false, false, false, false><<<256, 256>>>(
            wq_c + l * DD, nullptr, nullptr, px, ln2_g + l * Dm, ln2_b + l * Dm,
            pqc, Dm, 256, 0, 0);
        t_kernel<<<1024, 256>>>(wk_c + l * DD);
        scores2<<<55, 256>>>(enc);
        // u = softmax(scores) @ E, softmax fused
        mv2<false, false, false, false, false, true><<<dim3(256, Hn), 256>>>(
            enc, enc, enc, psc, nullptr, nullptr, pu, ENCn, 256, ENCn, Dm);
        mv2<false, false, false, true, false, false><<<256, 256>>>(
            wv_c + l * DD, nullptr, nullptr, pu, nullptr, nullptr, patto, Dm, 256, 0, 0);
        mv2<false, false, true, false, false, false><<<256, 256>>>(
            wo_c + l * DD, nullptr, nullptr, patto, nullptr, nullptr, px, Dm, 256, 0, 0);
        // --- FFN ---
        mv2<true, true, false, false, false, false><<<1024, 256>>>(
            w1 + (size_t)l * Dm * Fn, nullptr, nullptr, px, ln3_g + l * Dm, ln3_b + l * Dm,
            pffn, Dm, 1024, 0, 0);
        mv2<false, false, true, false, false, false><<<256, 256>>>(
            w2 + (size_t)l * Fn * Dm, nullptr, nullptr, pffn, nullptr, nullptr,
            px, Fn, 256, 0, 0);
    }

    lm_head_kernel<<<2048, 256>>>(emb, lnf_g, lnf_b, out);
}

// round 4
// speedup vs baseline: 1.5532x; 1.2301x over previous
#include <cuda_runtime.h>
#include <cstdint>
#include <math.h>

#define Dm 1024
#define Hn 8
#define DHn 128
#define Fn 4096
#define Vn 16384
#define ENCn 438
#define PASTn 447
#define TOTn 448
#define Lnum 8
#define NSPLIT 14
#define ATT_SCALE 0.08838834764831845f

// ---------------- device scratch ----------------
__device__ float g_x[Dm];
__device__ float g_qkv[3 * Dm];
__device__ float g_att_o[Dm];
__device__ float g_qc[Dm];
__device__ float g_t[Hn * Dm];
__device__ float g_sc[Hn * ENCn];
__device__ float g_u[Hn * Dm];
__device__ float g_ffn[Fn];
__device__ float g_po[Hn * NSPLIT * DHn];
__device__ float g_pm[Hn * NSPLIT];
__device__ float g_ps[Hn * NSPLIT];

__device__ __forceinline__ float gelu_f(float v) {
    float c = v * v * v;
    return 0.5f * v * (1.0f + tanhf(0.7978845608028654f * (v + 0.044715f * c)));
}

// ---------------- embedding ----------------
__global__ void embed_kernel(const int* __restrict__ ids,
                             const float* __restrict__ emb,
                             const float* __restrict__ pos) {
    int t = threadIdx.x;  // 256
    int id = ids[0];
    const float4* e4 = (const float4*)(emb + (size_t)id * Dm);
    const float4* p4 = (const float4*)(pos + (size_t)PASTn * Dm);
    float4 a = e4[t], b = p4[t];
    a.x += b.x; a.y += b.y; a.z += b.z; a.w += b.w;
    ((float4*)g_x)[t] = a;
}

// ---------------- per-layer zero of atomic accumulators -------------------
// segments (float4 units): qkv 768, qc 256, att_o 256, u 2048, ffn 1024 = 4352
__global__ void zero_kernel() {
    int i = blockIdx.x * 256 + threadIdx.x;  // 17 x 256 = 4352
    float4 z = make_float4(0.f, 0.f, 0.f, 0.f);
    if (i < 768) { ((float4*)g_qkv)[i] = z; return; }
    i -= 768;
    if (i < 256) { ((float4*)g_qc)[i] = z; return; }
    i -= 256;
    if (i < 256) { ((float4*)g_att_o)[i] = z; return; }
    i -= 256;
    if (i < 2048) { ((float4*)g_u)[i] = z; return; }
    i -= 2048;
    ((float4*)g_ffn)[i] = z;
}

// ---------------- split matvec, coalesced, atomic accumulate --------------
// Block: 256 threads = 8 warps. Block covers 128 consecutive outputs
// (lane = output quad). Warps stride over the block's row slice
// [blockIdx.y*rps, +rps). Partial sums atomicAdd'ed into out.
// MODE: 0 raw copy, 1 layernorm (din==1024), 2 split-KV combine,
//       3 softmax (din==ENCn), 4 gelu.
template <int MODE, bool PERHEAD>
__global__ void mvs(const float* __restrict__ Wa,
                    const float* __restrict__ Wb,
                    const float* __restrict__ Wc,
                    const float* __restrict__ xin,
                    const float* __restrict__ gamma,
                    const float* __restrict__ beta,
                    float* __restrict__ out,
                    int din, int dout4, int rps, int xstride, int ostride) {
    __shared__ float sx[1024];
    __shared__ float4 sacc[8][32];
    __shared__ float wred[8];
    int tid = threadIdx.x, w = tid >> 5, lane = tid & 31;
    int y = blockIdx.z;
    const float* W = (y == 1) ? Wb : ((y == 2) ? Wc : Wa);
    const float* xe = xin + (size_t)y * xstride;
    if (PERHEAD) xe += (size_t)blockIdx.x * Dm;  // dout==1024, 128 out/block

    int rowBase = blockIdx.y * rps;
    int rowEnd = rowBase + rps;
    if (rowEnd > din) rowEnd = din;

    if (MODE == 1) {
        // layernorm of full 1024-vector; store full normalized vector
        float4 xv = ((const float4*)xe)[tid];
        float s = xv.x + xv.y + xv.z + xv.w;
        #pragma unroll
        for (int m = 16; m >= 1; m >>= 1) s += __shfl_xor_sync(0xffffffffu, s, m);
        if (lane == 0) wred[w] = s;
        __syncthreads();
        float mean = 0.0f;
        #pragma unroll
        for (int i = 0; i < 8; i++) mean += wred[i];
        mean *= (1.0f / 1024.0f);
        float4 dv;
        dv.x = xv.x - mean; dv.y = xv.y - mean; dv.z = xv.z - mean; dv.w = xv.w - mean;
        float s2 = dv.x * dv.x + dv.y * dv.y + dv.z * dv.z + dv.w * dv.w;
        #pragma unroll
        for (int m = 16; m >= 1; m >>= 1) s2 += __shfl_xor_sync(0xffffffffu, s2, m);
        __syncthreads();
        if (lane == 0) wred[w] = s2;
        __syncthreads();
        float var = 0.0f;
        #pragma unroll
        for (int i = 0; i < 8; i++) var += wred[i];
        float rstd = rsqrtf(var * (1.0f / 1024.0f) + 1e-5f);
        float4 g4 = ((const float4*)gamma)[tid];
        float4 b4 = ((const float4*)beta)[tid];
        float4 o;
        o.x = dv.x * rstd * g4.x + b4.x;
        o.y = dv.y * rstd * g4.y + b4.y;
        o.z = dv.z * rstd * g4.z + b4.z;
        o.w = dv.w * rstd * g4.w + b4.w;
        ((float4*)sx)[tid] = o;
        __syncthreads();
    } else if (MODE == 2) {
        // split-KV combine for the block's row slice
        __shared__ float spm[Hn * NSPLIT];
        __shared__ float sps[Hn * NSPLIT];
        if (tid < Hn * NSPLIT) { spm[tid] = g_pm[tid]; sps[tid] = g_ps[tid]; }
        __syncthreads();
        for (int idx = tid; idx < rowEnd - rowBase; idx += 256) {
            int row = rowBase + idx;
            int h = row >> 7, c = row & 127;
            float M = -1e30f;
            #pragma unroll
            for (int s = 0; s < NSPLIT; s++) M = fmaxf(M, spm[h * NSPLIT + s]);
            float S = 0.0f, o = 0.0f;
            #pragma unroll
            for (int s = 0; s < NSPLIT; s++) {
                float wv = expf(spm[h * NSPLIT + s] - M);
                S += sps[h * NSPLIT + s] * wv;
                o += g_po[(h * NSPLIT + s) * DHn + c] * wv;
            }
            sx[idx] = o / S;
        }
        __syncthreads();
    } else if (MODE == 3) {
        // softmax over full 438; store normalized probs for row slice
        float v0 = (tid < ENCn) ? xe[tid] : -1e30f;
        float v1 = (tid + 256 < ENCn) ? xe[tid + 256] : -1e30f;
        float m = fmaxf(v0, v1);
        #pragma unroll
        for (int s = 16; s >= 1; s >>= 1) m = fmaxf(m, __shfl_xor_sync(0xffffffffu, m, s));
        if (lane == 0) wred[w] = m;
        __syncthreads();
        float M = wred[0];
        #pragma unroll
        for (int i = 1; i < 8; i++) M = fmaxf(M, wred[i]);
        float e0 = (tid < ENCn) ? expf(v0 - M) : 0.0f;
        float e1 = (tid + 256 < ENCn) ? expf(v1 - M) : 0.0f;
        float s = e0 + e1;
        #pragma unroll
        for (int mm = 16; mm >= 1; mm >>= 1) s += __shfl_xor_sync(0xffffffffu, s, mm);
        __syncthreads();
        if (lane == 0) wred[w] = s;
        __syncthreads();
        float S = 0.0f;
        #pragma unroll
        for (int i = 0; i < 8; i++) S += wred[i];
        float inv = 1.0f / S;
        for (int idx = tid; idx < rowEnd - rowBase; idx += 256)
            sx[idx] = expf(xe[rowBase + idx] - M) * inv;
        __syncthreads();
    } else if (MODE == 4) {
        for (int idx = tid; idx < rowEnd - rowBase; idx += 256)
            sx[idx] = gelu_f(xe[rowBase + idx]);
        __syncthreads();
    } else {
        for (int idx = tid; idx < rowEnd - rowBase; idx += 256)
            sx[idx] = xe[rowBase + idx];
        __syncthreads();
    }

    // main loop: lane owns output quad, warps stride rows -> 512B/warp loads
    const float4* W4 = (const float4*)W;
    int q = blockIdx.x * 32 + lane;
    float4 acc = make_float4(0.f, 0.f, 0.f, 0.f);
    #pragma unroll 4
    for (int r = rowBase + w; r < rowEnd; r += 8) {
        float xv = (MODE == 1) ? sx[r] : sx[r - rowBase];
        float4 wv = W4[(size_t)r * dout4 + q];
        acc.x += xv * wv.x; acc.y += xv * wv.y;
        acc.z += xv * wv.z; acc.w += xv * wv.w;
    }
    sacc[w][lane] = acc;
    __syncthreads();
    if (tid < 32) {
        float4 t = sacc[0][tid];
        #pragma unroll
        for (int i = 1; i < 8; i++) {
            float4 a = sacc[i][tid];
            t.x += a.x; t.y += a.y; t.z += a.z; t.w += a.w;
        }
        float* op = out + (size_t)y * ostride + blockIdx.x * 128 + tid * 4;
        atomicAdd(op + 0, t.x);
        atomicAdd(op + 1, t.y);
        atomicAdd(op + 2, t.z);
        atomicAdd(op + 3, t.w);
    }
}

// ---------------- self attention: split-KV flash, grid (NSPLIT, Hn) -------
__global__ void attnA(const float* __restrict__ past_k,
                      const float* __restrict__ past_v) {
    int split = blockIdx.x, h = blockIdx.y;
    int base = split * 32;
    int tid = threadIdx.x;  // 256
    int warp = tid >> 5, lane = tid & 31;
    __shared__ float q[DHn];
    __shared__ float sc[32];
    __shared__ float red[256];
    __shared__ float ms[2];
    if (tid < DHn) q[tid] = g_qkv[h * DHn + tid];
    __syncthreads();

    #pragma unroll
    for (int r = 0; r < 4; r++) {
        int p = base + warp * 4 + r;
        const float* krow = (p < PASTn) ? past_k + ((size_t)h * PASTn + p) * DHn
                                        : g_qkv + Dm + h * DHn;
        float4 k4 = ((const float4*)krow)[lane];
        float4 q4 = ((const float4*)q)[lane];
        float d = k4.x * q4.x + k4.y * q4.y + k4.z * q4.z + k4.w * q4.w;
        #pragma unroll
        for (int m = 16; m >= 1; m >>= 1) d += __shfl_xor_sync(0xffffffffu, d, m);
        if (lane == 0) sc[warp * 4 + r] = d * ATT_SCALE;
    }
    __syncthreads();

    if (warp == 0) {
        float v = sc[lane];
        float mloc = v;
        #pragma unroll
        for (int m = 16; m >= 1; m >>= 1)
            mloc = fmaxf(mloc, __shfl_xor_sync(0xffffffffu, mloc, m));
        float e = expf(v - mloc);
        float s = e;
        #pragma unroll
        for (int m = 16; m >= 1; m >>= 1) s += __shfl_xor_sync(0xffffffffu, s, m);
        sc[lane] = e;
        if (lane == 0) { ms[0] = mloc; ms[1] = s; }
    }
    __syncthreads();

    int c = tid & 127, pg = tid >> 7;
    float acc = 0.0f;
    #pragma unroll 4
    for (int pp = pg * 16; pp < pg * 16 + 16; pp++) {
        int p = base + pp;
        const float* vrow = (p < PASTn) ? past_v + ((size_t)h * PASTn + p) * DHn
                                        : g_qkv + 2 * Dm + h * DHn;
        acc += sc[pp] * vrow[c];
    }
    red[tid] = acc;
    __syncthreads();
    if (pg == 0) {
        g_po[(h * NSPLIT + split) * DHn + c] = red[c] + red[c + 128];
        if (c == 0) { g_pm[h * NSPLIT + split] = ms[0]; g_ps[h * NSPLIT + split] = ms[1]; }
    }
}

// ---------------- t[h][d] = dot(qc_h, wk[d, h*128:+128]) -----------------
// Row-dot kernel: each wk row (4KB) read once, serves all 8 heads.
// grid = 64 blocks x 256 threads; warp handles 2 rows.
__global__ void tker(const float* __restrict__ wk) {
    __shared__ float sq[Dm];
    int tid = threadIdx.x, w = tid >> 5, lane = tid & 31;
    ((float4*)sq)[tid] = ((const float4*)g_qc)[tid];
    __syncthreads();
    #pragma unroll
    for (int rr = 0; rr < 2; rr++) {
        int d = blockIdx.x * 16 + w * 2 + rr;
        const float4* row = (const float4*)(wk + (size_t)d * Dm);
        float acc[Hn];
        #pragma unroll
        for (int h = 0; h < Hn; h++) {
            float4 w4 = row[h * 32 + lane];
            float4 q4 = ((const float4*)sq)[h * 32 + lane];
            acc[h] = w4.x * q4.x + w4.y * q4.y + w4.z * q4.z + w4.w * q4.w;
        }
        #pragma unroll
        for (int h = 0; h < Hn; h++) {
            #pragma unroll
            for (int m = 16; m >= 1; m >>= 1)
                acc[h] += __shfl_xor_sync(0xffffffffu, acc[h], m);
        }
        if (lane < Hn) g_t[lane * Dm + d] = acc[lane];
    }
}

// ---------------- scores: warp per encoder row, 8 heads per warp ---------
__global__ void scores2(const float* __restrict__ E) {
    __shared__ float st[Hn * Dm];
    int tid = threadIdx.x;
    for (int i = tid; i < Hn * Dm / 4; i += 256)
        ((float4*)st)[i] = ((const float4*)g_t)[i];
    __syncthreads();
    int e = blockIdx.x * 8 + (tid >> 5);
    int lane = tid & 31;
    if (e >= ENCn) return;
    const float4* erow = (const float4*)(E + (size_t)e * Dm);
    float acc[Hn];
    #pragma unroll
    for (int h = 0; h < Hn; h++) acc[h] = 0.0f;
    #pragma unroll
    for (int r = 0; r < 8; r++) {
        float4 e4 = erow[r * 32 + lane];
        #pragma unroll
        for (int h = 0; h < Hn; h++) {
            float4 t4 = ((const float4*)(st + h * Dm))[r * 32 + lane];
            acc[h] += e4.x * t4.x + e4.y * t4.y + e4.z * t4.z + e4.w * t4.w;
        }
    }
    #pragma unroll
    for (int h = 0; h < Hn; h++) {
        #pragma unroll
        for (int m = 16; m >= 1; m >>= 1)
            acc[h] += __shfl_xor_sync(0xffffffffu, acc[h], m);
    }
    if (lane == 0) {
        #pragma unroll
        for (int h = 0; h < Hn; h++) g_sc[h * ENCn + e] = acc[h] * ATT_SCALE;
    }
}

// ---------------- final LN + tied lm_head --------------------------------
__global__ void lm_head_kernel(const float* __restrict__ emb,
                               const float* __restrict__ gamma,
                               const float* __restrict__ beta,
                               float* __restrict__ out) {
    __shared__ float hx[Dm];
    __shared__ float red[256];
    int tid = threadIdx.x;
    float v[4];
    float s = 0.0f;
    #pragma unroll
    for (int r = 0; r < 4; r++) { v[r] = g_x[tid + r * 256]; s += v[r]; }
    red[tid] = s;
    __syncthreads();
    #pragma unroll
    for (int st = 128; st >= 1; st >>= 1) {
        if (tid < st) red[tid] += red[tid + st];
        __syncthreads();
    }
    float mean = red[0] * (1.0f / 1024.0f);
    __syncthreads();
    s = 0.0f;
    #pragma unroll
    for (int r = 0; r < 4; r++) { v[r] -= mean; s += v[r] * v[r]; }
    red[tid] = s;
    __syncthreads();
    #pragma unroll
    for (int st = 128; st >= 1; st >>= 1) {
        if (tid < st) red[tid] += red[tid + st];
        __syncthreads();
    }
    float inv = rsqrtf(red[0] * (1.0f / 1024.0f) + 1e-5f);
    __syncthreads();
    #pragma unroll
    for (int r = 0; r < 4; r++)
        hx[tid + r * 256] = v[r] * inv * gamma[tid + r * 256] + beta[tid + r * 256];
    __syncthreads();

    int gw = blockIdx.x * 8 + (tid >> 5);
    int lane = tid & 31;
    const float4* erow = (const float4*)(emb + (size_t)gw * Dm);
    const float4* hx4 = (const float4*)hx;
    float acc = 0.0f;
    #pragma unroll
    for (int r = 0; r < 8; r++) {
        float4 e4 = erow[r * 32 + lane];
        float4 h4 = hx4[r * 32 + lane];
        acc += e4.x * h4.x + e4.y * h4.y + e4.z * h4.z + e4.w * h4.w;
    }
    #pragma unroll
    for (int st = 16; st >= 1; st >>= 1) acc += __shfl_xor_sync(0xffffffffu, acc, st);
    if (lane == 0) out[gw] = acc;
}

// ---------------- launch ----------------
extern "C" void kernel_launch(void* const* d_in, const int* in_sizes, int n_in,
                              void* d_out, int out_size) {
    const int*   ids    = (const int*)d_in[0];
    const float* enc    = (const float*)d_in[1];
    const float* past_k = (const float*)d_in[2];
    const float* past_v = (const float*)d_in[3];
    const float* emb    = (const float*)d_in[4];
    const float* pos    = (const float*)d_in[5];
    const float* ln1_g  = (const float*)d_in[6];
    const float* ln1_b  = (const float*)d_in[7];
    const float* wq_s   = (const float*)d_in[8];
    const float* wk_s   = (const float*)d_in[9];
    const float* wv_s   = (const float*)d_in[10];
    const float* wo_s   = (const float*)d_in[11];
    const float* ln2_g  = (const float*)d_in[12];
    const float* ln2_b  = (const float*)d_in[13];
    const float* wq_c   = (const float*)d_in[14];
    const float* wk_c   = (const float*)d_in[15];
    const float* wv_c   = (const float*)d_in[16];
    const float* wo_c   = (const float*)d_in[17];
    const float* ln3_g  = (const float*)d_in[18];
    const float* ln3_b  = (const float*)d_in[19];
    const float* w1     = (const float*)d_in[20];
    const float* w2     = (const float*)d_in[21];
    const float* lnf_g  = (const float*)d_in[22];
    const float* lnf_b  = (const float*)d_in[23];
    float* out = (float*)d_out;

    float *px, *pqkv, *patto, *pqc, *psc, *pu, *pffn;
    cudaGetSymbolAddress((void**)&px,    g_x);
    cudaGetSymbolAddress((void**)&pqkv,  g_qkv);
    cudaGetSymbolAddress((void**)&patto, g_att_o);
    cudaGetSymbolAddress((void**)&pqc,   g_qc);
    cudaGetSymbolAddress((void**)&psc,   g_sc);
    cudaGetSymbolAddress((void**)&pu,    g_u);
    cudaGetSymbolAddress((void**)&pffn,  g_ffn);

    const size_t DD = (size_t)Dm * Dm;
    const size_t KVL = (size_t)Hn * PASTn * DHn;

    embed_kernel<<<1, 256>>>(ids, emb, pos);

    for (int l = 0; l < Lnum; l++) {
        zero_kernel<<<17, 256>>>();
        // fused LN1 + q,k,v projections
        mvs<1, false><<<dim3(8, 8, 3), 256>>>(
            wq_s + l * DD, wk_s + l * DD, wv_s + l * DD,
            px, ln1_g + l * Dm, ln1_b + l * Dm, pqkv, Dm, 256, 128, 0, Dm);
        attnA<<<dim3(NSPLIT, Hn), 256>>>(past_k + l * KVL, past_v + l * KVL);
        // o-proj with per-slice split-KV combine; accumulates into x (residual)
        mvs<2, false><<<dim3(8, 16, 1), 256>>>(
            wo_s + l * DD, nullptr, nullptr, px, nullptr, nullptr,
            px, Dm, 256, 64, 0, 0);
        // LN2 + cross q
        mvs<1, false><<<dim3(8, 16, 1), 256>>>(
            wq_c + l * DD, nullptr, nullptr, px, ln2_g + l * Dm, ln2_b + l * Dm,
            pqc, Dm, 256, 64, 0, 0);
        tker<<<64, 256>>>(wk_c + l * DD);
        scores2<<<55, 256>>>(enc);
        // u = softmax(scores) @ E (softmax fused, per head)
        mvs<3, false><<<dim3(8, 2, 8), 256>>>(
            enc, enc, enc, psc, nullptr, nullptr, pu, ENCn, 256, 219, ENCn, Dm);
        // att_o = u @ wv_c (per-head input slice)
        mvs<0, true><<<dim3(8, 16, 1), 256>>>(
            wv_c + l * DD, nullptr, nullptr, pu, nullptr, nullptr,
            patto, Dm, 256, 64, 0, 0);
        // x += att_o @ wo_c
        mvs<0, false><<<dim3(8, 16, 1), 256>>>(
            wo_c + l * DD, nullptr, nullptr, patto, nullptr, nullptr,
            px, Dm, 256, 64, 0, 0);
        // ffn: h = LN3(x) @ w1 (gelu applied by consumer)
        mvs<1, false><<<dim3(32, 8, 1), 256>>>(
            w1 + (size_t)l * Dm * Fn, nullptr, nullptr, px,
            ln3_g + l * Dm, ln3_b + l * Dm, pffn, Dm, 1024, 128, 0, 0);
        // x += gelu(h) @ w2
        mvs<4, false><<<dim3(8, 32, 1), 256>>>(
            w2 + (size_t)l * Fn * Dm, nullptr, nullptr, pffn, nullptr, nullptr,
            px, Fn, 256, 128, 0, 0);
    }

    lm_head_kernel<<<2048, 256>>>(emb, lnf_g, lnf_b, out);
}

// round 5
// speedup vs baseline: 1.6070x; 1.0346x over previous
#include <cuda_runtime.h>
#include <cstdint>
#include <math.h>

#define Dm 1024
#define Hn 8
#define DHn 128
#define Fn 4096
#define Vn 16384
#define ENCn 438
#define PASTn 447
#define TOTn 448
#define Lnum 8
#define NSPLIT 28
#define SPLEN 16
#define ATT_SCALE 0.08838834764831845f

// ---------------- device scratch ----------------
__device__ float g_x[Dm];
__device__ float g_qkv[3 * Dm];
__device__ float g_att_o[Dm];
__device__ float g_qc[Dm];
__device__ float g_t[Hn * Dm];
__device__ float g_sc[Hn * ENCn];
__device__ float g_u[Hn * Dm];
__device__ float g_ffn[Fn];
__device__ float g_po[Hn * NSPLIT * DHn];
__device__ float g_pm[Hn * NSPLIT];
__device__ float g_ps[Hn * NSPLIT];

__device__ __forceinline__ float gelu_f(float v) {
    float c = v * v * v;
    return 0.5f * v * (1.0f + tanhf(0.7978845608028654f * (v + 0.044715f * c)));
}

// zero helper for the 3584-float4 accumulator set {qc, att_o, u, ffn}
__device__ __forceinline__ void zstore_acc(int i) {
    float4 z = make_float4(0.f, 0.f, 0.f, 0.f);
    if (i < 256) { ((float4*)g_qc)[i] = z; return; }
    i -= 256;
    if (i < 256) { ((float4*)g_att_o)[i] = z; return; }
    i -= 256;
    if (i < 2048) { ((float4*)g_u)[i] = z; return; }
    i -= 2048;
    if (i < 1024) ((float4*)g_ffn)[i] = z;
}

// ---------------- embedding + zero-all ----------------
// block 0: x = emb[id] + pos[PAST]; blocks 1..17: zero qkv/qc/att_o/u/ffn
__global__ void embed_kernel(const int* __restrict__ ids,
                             const float* __restrict__ emb,
                             const float* __restrict__ pos) {
    int t = threadIdx.x;  // 256
    if (blockIdx.x == 0) {
        int id = ids[0];
        const float4* e4 = (const float4*)(emb + (size_t)id * Dm);
        const float4* p4 = (const float4*)(pos + (size_t)PASTn * Dm);
        float4 a = e4[t], b = p4[t];
        a.x += b.x; a.y += b.y; a.z += b.z; a.w += b.w;
        ((float4*)g_x)[t] = a;
        return;
    }
    int i = (blockIdx.x - 1) * 256 + t;  // 0..4351
    float4 z = make_float4(0.f, 0.f, 0.f, 0.f);
    if (i < 768) { ((float4*)g_qkv)[i] = z; return; }
    zstore_acc(i - 768);
}

// ---------------- split matvec, coalesced, atomic accumulate --------------
// Block: 256 threads = 8 warps; 128 consecutive outputs (lane = output quad).
// Warps stride over row slice [blockIdx.y*rps, +rps). atomicAdd into out.
// MODE: 0 raw, 1 layernorm (din==1024), 2 split-KV combine, 3 softmax, 4 gelu.
template <int MODE, bool PERHEAD>
__global__ void mvs(const float* __restrict__ Wa,
                    const float* __restrict__ Wb,
                    const float* __restrict__ Wc,
                    const float* __restrict__ xin,
                    const float* __restrict__ gamma,
                    const float* __restrict__ beta,
                    float* __restrict__ out,
                    int din, int dout4, int rps, int xstride, int ostride) {
    __shared__ float sx[1024];
    __shared__ float4 sacc[8][32];
    __shared__ float wred[8];
    int tid = threadIdx.x, w = tid >> 5, lane = tid & 31;
    int y = blockIdx.z;
    const float* W = (y == 1) ? Wb : ((y == 2) ? Wc : Wa);
    const float* xe = xin + (size_t)y * xstride;
    if (PERHEAD) xe += (size_t)blockIdx.x * Dm;

    int rowBase = blockIdx.y * rps;
    int rowEnd = rowBase + rps;
    if (rowEnd > din) rowEnd = din;

    if (MODE == 1) {
        float4 xv = ((const float4*)xe)[tid];
        float s = xv.x + xv.y + xv.z + xv.w;
        #pragma unroll
        for (int m = 16; m >= 1; m >>= 1) s += __shfl_xor_sync(0xffffffffu, s, m);
        if (lane == 0) wred[w] = s;
        __syncthreads();
        float mean = 0.0f;
        #pragma unroll
        for (int i = 0; i < 8; i++) mean += wred[i];
        mean *= (1.0f / 1024.0f);
        float4 dv;
        dv.x = xv.x - mean; dv.y = xv.y - mean; dv.z = xv.z - mean; dv.w = xv.w - mean;
        float s2 = dv.x * dv.x + dv.y * dv.y + dv.z * dv.z + dv.w * dv.w;
        #pragma unroll
        for (int m = 16; m >= 1; m >>= 1) s2 += __shfl_xor_sync(0xffffffffu, s2, m);
        __syncthreads();
        if (lane == 0) wred[w] = s2;
        __syncthreads();
        float var = 0.0f;
        #pragma unroll
        for (int i = 0; i < 8; i++) var += wred[i];
        float rstd = rsqrtf(var * (1.0f / 1024.0f) + 1e-5f);
        float4 g4 = ((const float4*)gamma)[tid];
        float4 b4 = ((const float4*)beta)[tid];
        float4 o;
        o.x = dv.x * rstd * g4.x + b4.x;
        o.y = dv.y * rstd * g4.y + b4.y;
        o.z = dv.z * rstd * g4.z + b4.z;
        o.w = dv.w * rstd * g4.w + b4.w;
        ((float4*)sx)[tid] = o;
        __syncthreads();
    } else if (MODE == 2) {
        __shared__ float spm[Hn * NSPLIT];
        __shared__ float sps[Hn * NSPLIT];
        if (tid < Hn * NSPLIT) { spm[tid] = g_pm[tid]; sps[tid] = g_ps[tid]; }
        __syncthreads();
        for (int idx = tid; idx < rowEnd - rowBase; idx += 256) {
            int row = rowBase + idx;
            int h = row >> 7, c = row & 127;
            float M = -1e30f;
            #pragma unroll
            for (int s = 0; s < NSPLIT; s++) M = fmaxf(M, spm[h * NSPLIT + s]);
            float S = 0.0f, o = 0.0f;
            #pragma unroll
            for (int s = 0; s < NSPLIT; s++) {
                float wv = expf(spm[h * NSPLIT + s] - M);
                S += sps[h * NSPLIT + s] * wv;
                o += g_po[(h * NSPLIT + s) * DHn + c] * wv;
            }
            sx[idx] = o / S;
        }
        __syncthreads();
    } else if (MODE == 3) {
        float v0 = (tid < ENCn) ? xe[tid] : -1e30f;
        float v1 = (tid + 256 < ENCn) ? xe[tid + 256] : -1e30f;
        float m = fmaxf(v0, v1);
        #pragma unroll
        for (int s = 16; s >= 1; s >>= 1) m = fmaxf(m, __shfl_xor_sync(0xffffffffu, m, s));
        if (lane == 0) wred[w] = m;
        __syncthreads();
        float M = wred[0];
        #pragma unroll
        for (int i = 1; i < 8; i++) M = fmaxf(M, wred[i]);
        float e0 = (tid < ENCn) ? expf(v0 - M) : 0.0f;
        float e1 = (tid + 256 < ENCn) ? expf(v1 - M) : 0.0f;
        float s = e0 + e1;
        #pragma unroll
        for (int mm = 16; mm >= 1; mm >>= 1) s += __shfl_xor_sync(0xffffffffu, s, mm);
        __syncthreads();
        if (lane == 0) wred[w] = s;
        __syncthreads();
        float S = 0.0f;
        #pragma unroll
        for (int i = 0; i < 8; i++) S += wred[i];
        float inv = 1.0f / S;
        for (int idx = tid; idx < rowEnd - rowBase; idx += 256)
            sx[idx] = expf(xe[rowBase + idx] - M) * inv;
        __syncthreads();
    } else if (MODE == 4) {
        for (int idx = tid; idx < rowEnd - rowBase; idx += 256)
            sx[idx] = gelu_f(xe[rowBase + idx]);
        __syncthreads();
    } else {
        for (int idx = tid; idx < rowEnd - rowBase; idx += 256)
            sx[idx] = xe[rowBase + idx];
        __syncthreads();
    }

    const float4* W4 = (const float4*)W;
    int q = blockIdx.x * 32 + lane;
    float4 acc = make_float4(0.f, 0.f, 0.f, 0.f);
    #pragma unroll 8
    for (int r = rowBase + w; r < rowEnd; r += 8) {
        float xv = (MODE == 1) ? sx[r] : sx[r - rowBase];
        float4 wv = W4[(size_t)r * dout4 + q];
        acc.x += xv * wv.x; acc.y += xv * wv.y;
        acc.z += xv * wv.z; acc.w += xv * wv.w;
    }
    sacc[w][lane] = acc;
    __syncthreads();
    if (tid < 32) {
        float4 t = sacc[0][tid];
        #pragma unroll
        for (int i = 1; i < 8; i++) {
            float4 a = sacc[i][tid];
            t.x += a.x; t.y += a.y; t.z += a.z; t.w += a.w;
        }
        float* op = out + (size_t)y * ostride + blockIdx.x * 128 + tid * 4;
        atomicAdd(op + 0, t.x);
        atomicAdd(op + 1, t.y);
        atomicAdd(op + 2, t.z);
        atomicAdd(op + 3, t.w);
    }
}

// ---------------- self attention: split-KV flash v2 -----------------------
// grid (NSPLIT+2, Hn), block 128. blockIdx.x < NSPLIT: compute 16 positions.
// blockIdx.x >= NSPLIT: zero next-stage accumulators (qc/att_o/u/ffn).
__global__ void attnA(const float* __restrict__ past_k,
                      const float* __restrict__ past_v) {
    int tid = threadIdx.x;
    if (blockIdx.x >= NSPLIT) {
        int zid = (blockIdx.x - NSPLIT) * Hn + blockIdx.y;  // 0..15
        int base = zid * 224;
        zstore_acc(base + tid);
        if (tid < 96) zstore_acc(base + 128 + tid);
        return;
    }
    int split = blockIdx.x, h = blockIdx.y;
    int base = split * SPLEN;
    int w = tid >> 5, lane = tid & 31;
    __shared__ float q[DHn];
    __shared__ float sc[SPLEN];
    __shared__ float ms[2];
    q[tid] = g_qkv[h * DHn + tid];
    __syncthreads();

    // dot phase: warp w -> positions base + w*4 .. +3, batch loads first
    float4 k4[4];
    #pragma unroll
    for (int r = 0; r < 4; r++) {
        int p = base + w * 4 + r;
        const float* krow = (p < PASTn) ? past_k + ((size_t)h * PASTn + p) * DHn
                                        : g_qkv + Dm + h * DHn;
        k4[r] = ((const float4*)krow)[lane];
    }
    float4 q4 = ((const float4*)q)[lane];
    #pragma unroll
    for (int r = 0; r < 4; r++) {
        float d = k4[r].x * q4.x + k4[r].y * q4.y + k4[r].z * q4.z + k4[r].w * q4.w;
        #pragma unroll
        for (int m = 16; m >= 1; m >>= 1) d += __shfl_xor_sync(0xffffffffu, d, m);
        if (lane == 0) sc[w * 4 + r] = d * ATT_SCALE;
    }
    __syncthreads();

    // softmax over 16 (warp 0, lanes 0..15)
    if (tid < 32) {
        float v = (lane < SPLEN) ? sc[lane] : -1e30f;
        float mloc = v;
        #pragma unroll
        for (int m = 8; m >= 1; m >>= 1)
            mloc = fmaxf(mloc, __shfl_xor_sync(0xffffffffu, mloc, m));
        float e = (lane < SPLEN) ? expf(v - mloc) : 0.0f;
        float s = e;
        #pragma unroll
        for (int m = 8; m >= 1; m >>= 1) s += __shfl_xor_sync(0xffffffffu, s, m);
        if (lane < SPLEN) sc[lane] = e;
        if (lane == 0) { ms[0] = mloc; ms[1] = s; }
    }
    __syncthreads();

    // V phase: thread = dim c, 16 independent position loads
    float acc = 0.0f;
    #pragma unroll
    for (int pp = 0; pp < SPLEN; pp++) {
        int p = base + pp;
        const float* vrow = (p < PASTn) ? past_v + ((size_t)h * PASTn + p) * DHn
                                        : g_qkv + 2 * Dm + h * DHn;
        acc += sc[pp] * vrow[tid];
    }
    g_po[(h * NSPLIT + split) * DHn + tid] = acc;
    if (tid == 0) { g_pm[h * NSPLIT + split] = ms[0]; g_ps[h * NSPLIT + split] = ms[1]; }
}

// ---------------- t[h][d] = dot(qc_h, wk[d, h*128:+128]) -----------------
__global__ void tker(const float* __restrict__ wk) {
    __shared__ float sq[Dm];
    int tid = threadIdx.x, w = tid >> 5, lane = tid & 31;
    ((float4*)sq)[tid] = ((const float4*)g_qc)[tid];
    __syncthreads();
    #pragma unroll
    for (int rr = 0; rr < 2; rr++) {
        int d = blockIdx.x * 16 + w * 2 + rr;
        const float4* row = (const float4*)(wk + (size_t)d * Dm);
        float acc[Hn];
        #pragma unroll
        for (int h = 0; h < Hn; h++) {
            float4 w4 = row[h * 32 + lane];
            float4 q4 = ((const float4*)sq)[h * 32 + lane];
            acc[h] = w4.x * q4.x + w4.y * q4.y + w4.z * q4.z + w4.w * q4.w;
        }
        #pragma unroll
        for (int h = 0; h < Hn; h++) {
            #pragma unroll
            for (int m = 16; m >= 1; m >>= 1)
                acc[h] += __shfl_xor_sync(0xffffffffu, acc[h], m);
        }
        if (lane < Hn) g_t[lane * Dm + d] = acc[lane];
    }
}

// ---------------- scores + qkv zeroing ------------------------------------
// blocks 0..54: scores; blocks 55..57: zero g_qkv (dead: attnA already read it)
__global__ void scores2(const float* __restrict__ E) {
    int tid = threadIdx.x;
    if (blockIdx.x >= 55) {
        int i = (blockIdx.x - 55) * 256 + tid;  // 0..767
        ((float4*)g_qkv)[i] = make_float4(0.f, 0.f, 0.f, 0.f);
        return;
    }
    __shared__ float st[Hn * Dm];
    for (int i = tid; i < Hn * Dm / 4; i += 256)
        ((float4*)st)[i] = ((const float4*)g_t)[i];
    __syncthreads();
    int e = blockIdx.x * 8 + (tid >> 5);
    int lane = tid & 31;
    if (e >= ENCn) return;
    const float4* erow = (const float4*)(E + (size_t)e * Dm);
    float acc[Hn];
    #pragma unroll
    for (int h = 0; h < Hn; h++) acc[h] = 0.0f;
    #pragma unroll
    for (int r = 0; r < 8; r++) {
        float4 e4 = erow[r * 32 + lane];
        #pragma unroll
        for (int h = 0; h < Hn; h++) {
            float4 t4 = ((const float4*)(st + h * Dm))[r * 32 + lane];
            acc[h] += e4.x * t4.x + e4.y * t4.y + e4.z * t4.z + e4.w * t4.w;
        }
    }
    #pragma unroll
    for (int h = 0; h < Hn; h++) {
        #pragma unroll
        for (int m = 16; m >= 1; m >>= 1)
            acc[h] += __shfl_xor_sync(0xffffffffu, acc[h], m);
    }
    if (lane == 0) {
        #pragma unroll
        for (int h = 0; h < Hn; h++) g_sc[h * ENCn + e] = acc[h] * ATT_SCALE;
    }
}

// ---------------- final LN + tied lm_head --------------------------------
__global__ void lm_head_kernel(const float* __restrict__ emb,
                               const float* __restrict__ gamma,
                               const float* __restrict__ beta,
                               float* __restrict__ out) {
    __shared__ float hx[Dm];
    __shared__ float red[256];
    int tid = threadIdx.x;
    float v[4];
    float s = 0.0f;
    #pragma unroll
    for (int r = 0; r < 4; r++) { v[r] = g_x[tid + r * 256]; s += v[r]; }
    red[tid] = s;
    __syncthreads();
    #pragma unroll
    for (int st = 128; st >= 1; st >>= 1) {
        if (tid < st) red[tid] += red[tid + st];
        __syncthreads();
    }
    float mean = red[0] * (1.0f / 1024.0f);
    __syncthreads();
    s = 0.0f;
    #pragma unroll
    for (int r = 0; r < 4; r++) { v[r] -= mean; s += v[r] * v[r]; }
    red[tid] = s;
    __syncthreads();
    #pragma unroll
    for (int st = 128; st >= 1; st >>= 1) {
        if (tid < st) red[tid] += red[tid + st];
        __syncthreads();
    }
    float inv = rsqrtf(red[0] * (1.0f / 1024.0f) + 1e-5f);
    __syncthreads();
    #pragma unroll
    for (int r = 0; r < 4; r++)
        hx[tid + r * 256] = v[r] * inv * gamma[tid + r * 256] + beta[tid + r * 256];
    __syncthreads();

    int gw = blockIdx.x * 8 + (tid >> 5);
    int lane = tid & 31;
    const float4* erow = (const float4*)(emb + (size_t)gw * Dm);
    const float4* hx4 = (const float4*)hx;
    float acc = 0.0f;
    #pragma unroll
    for (int r = 0; r < 8; r++) {
        float4 e4 = erow[r * 32 + lane];
        float4 h4 = hx4[r * 32 + lane];
        acc += e4.x * h4.x + e4.y * h4.y + e4.z * h4.z + e4.w * h4.w;
    }
    #pragma unroll
    for (int st = 16; st >= 1; st >>= 1) acc += __shfl_xor_sync(0xffffffffu, acc, st);
    if (lane == 0) out[gw] = acc;
}

// ---------------- launch ----------------
extern "C" void kernel_launch(void* const* d_in, const int* in_sizes, int n_in,
                              void* d_out, int out_size) {
    const int*   ids    = (const int*)d_in[0];
    const float* enc    = (const float*)d_in[1];
    const float* past_k = (const float*)d_in[2];
    const float* past_v = (const float*)d_in[3];
    const float* emb    = (const float*)d_in[4];
    const float* pos    = (const float*)d_in[5];
    const float* ln1_g  = (const float*)d_in[6];
    const float* ln1_b  = (const float*)d_in[7];
    const float* wq_s   = (const float*)d_in[8];
    const float* wk_s   = (const float*)d_in[9];
    const float* wv_s   = (const float*)d_in[10];
    const float* wo_s   = (const float*)d_in[11];
    const float* ln2_g  = (const float*)d_in[12];
    const float* ln2_b  = (const float*)d_in[13];
    const float* wq_c   = (const float*)d_in[14];
    const float* wk_c   = (const float*)d_in[15];
    const float* wv_c   = (const float*)d_in[16];
    const float* wo_c   = (const float*)d_in[17];
    const float* ln3_g  = (const float*)d_in[18];
    const float* ln3_b  = (const float*)d_in[19];
    const float* w1     = (const float*)d_in[20];
    const float* w2     = (const float*)d_in[21];
    const float* lnf_g  = (const float*)d_in[22];
    const float* lnf_b  = (const float*)d_in[23];
    float* out = (float*)d_out;

    float *px, *pqkv, *patto, *pqc, *psc, *pu, *pffn;
    cudaGetSymbolAddress((void**)&px,    g_x);
    cudaGetSymbolAddress((void**)&pqkv,  g_qkv);
    cudaGetSymbolAddress((void**)&patto, g_att_o);
    cudaGetSymbolAddress((void**)&pqc,   g_qc);
    cudaGetSymbolAddress((void**)&psc,   g_sc);
    cudaGetSymbolAddress((void**)&pu,    g_u);
    cudaGetSymbolAddress((void**)&pffn,  g_ffn);

    const size_t DD = (size_t)Dm * Dm;
    const size_t KVL = (size_t)Hn * PASTn * DHn;

    embed_kernel<<<18, 256>>>(ids, emb, pos);

    for (int l = 0; l < Lnum; l++) {
        // fused LN1 + q,k,v projections
        mvs<1, false><<<dim3(8, 8, 3), 256>>>(
            wq_s + l * DD, wk_s + l * DD, wv_s + l * DD,
            px, ln1_g + l * Dm, ln1_b + l * Dm, pqkv, Dm, 256, 128, 0, Dm);
        // split-KV attention + zeroing of qc/att_o/u/ffn
        attnA<<<dim3(NSPLIT + 2, Hn), 128>>>(past_k + l * KVL, past_v + l * KVL);
        // o-proj with per-slice split-KV combine; accumulates into x
        mvs<2, false><<<dim3(8, 16, 1), 256>>>(
            wo_s + l * DD, nullptr, nullptr, px, nullptr, nullptr,
            px, Dm, 256, 64, 0, 0);
        // LN2 + cross q
        mvs<1, false><<<dim3(8, 16, 1), 256>>>(
            wq_c + l * DD, nullptr, nullptr, px, ln2_g + l * Dm, ln2_b + l * Dm,
            pqc, Dm, 256, 64, 0, 0);
        tker<<<64, 256>>>(wk_c + l * DD);
        scores2<<<58, 256>>>(enc);  // + qkv zeroing
        // u = softmax(scores) @ E (softmax fused, per head)
        mvs<3, false><<<dim3(8, 2, 8), 256>>>(
            enc, enc, enc, psc, nullptr, nullptr, pu, ENCn, 256, 219, ENCn, Dm);
        // att_o = u @ wv_c (per-head input slice)
        mvs<0, true><<<dim3(8, 16, 1), 256>>>(
            wv_c + l * DD, nullptr, nullptr, pu, nullptr, nullptr,
            patto, Dm, 256, 64, 0, 0);
        // x += att_o @ wo_c
        mvs<0, false><<<dim3(8, 16, 1), 256>>>(
            wo_c + l * DD, nullptr, nullptr, patto, nullptr, nullptr,
            px, Dm, 256, 64, 0, 0);
        // ffn: h = LN3(x) @ w1
        mvs<1, false><<<dim3(32, 8, 1), 256>>>(
            w1 + (size_t)l * Dm * Fn, nullptr, nullptr, px,
            ln3_g + l * Dm, ln3_b + l * Dm, pffn, Dm, 1024, 128, 0, 0);
        // x += gelu(h) @ w2
        mvs<4, false><<<dim3(8, 32, 1), 256>>>(
            w2 + (size_t)l * Fn * Dm, nullptr, nullptr, pffn, nullptr, nullptr,
            px, Fn, 256, 128, 0, 0);
    }

    lm_head_kernel<<<2048, 256>>>(emb, lnf_g, lnf_b, out);
}

// round 7
// speedup vs baseline: 1.7316x; 1.0775x over previous
#include <cuda_runtime.h>
#include <cstdint>
#include <math.h>

#define Dm 1024
#define Hn 8
#define DHn 128
#define Fn 4096
#define Vn 16384
#define ENCn 438
#define PASTn 447
#define TOTn 448
#define Lnum 8
#define NSPLIT 32
#define SPLEN 14
#define NB 296
#define ATT_SCALE 0.08838834764831845f

// ---------------- device scratch (no allocations) ----------------
__device__ float g_X[2][Dm];          // double-buffered residual stream
__device__ float g_PA[8 * 3072];      // qkv partials   [rs][3072]
__device__ float g_PB[8 * Dm];        // wo_s partials  [rs][1024]
__device__ float g_PC[8 * Dm];        // qc partials
__device__ float g_PD[8 * Dm];        // wv_c partials
__device__ float g_PE[8 * Dm];        // wo_c partials
__device__ float g_PF[8 * Fn];        // w1 partials    [rs][4096]
__device__ float g_PG[16 * Dm];       // w2 partials    [rs][1024]
__device__ float g_PU[4 * Hn * Dm];   // u partials     [rs][head][1024]
__device__ float g_t[Hn * Dm];
__device__ float g_sc[Hn * ENCn];
__device__ float g_po[Hn * NSPLIT * DHn];
__device__ float g_pm[Hn * NSPLIT];
__device__ float g_ps[Hn * NSPLIT];
__device__ int g_cnt;
__device__ volatile int g_gen;

__device__ __forceinline__ float gelu_f(float v) {
    float c = v * v * v;
    return 0.5f * v * (1.0f + tanhf(0.7978845608028654f * (v + 0.044715f * c)));
}
__device__ __forceinline__ float ldg1(const float* p) { return __ldcg(p); }
__device__ __forceinline__ float4 ldg4(const float* p) { return __ldcg((const float4*)p); }

// global software barrier; generation-relative (safe across graph replays)
__device__ __forceinline__ void gbar() {
    __syncthreads();
    if (threadIdx.x == 0) {
        __threadfence();
        int gen = g_gen;
        if (atomicAdd(&g_cnt, 1) == NB - 1) {
            g_cnt = 0;
            __threadfence();
            g_gen = gen + 1;
        } else {
            while (g_gen == gen) { __nanosleep(32); }
        }
    }
    __syncthreads();
}

// coalesced split matvec core. Block covers 128 consecutive outputs (group
// grp); rows [r0,r1); sxp[r-r0] = input; partial float4s written to dst.
__device__ __forceinline__ void mv_core(const float* __restrict__ W, int dout4,
                                        int grp, int r0, int r1,
                                        const float* sxp,
                                        float* __restrict__ dst,
                                        float4 (*s_acc)[32]) {
    int tid = threadIdx.x, w = tid >> 5, lane = tid & 31;
    const float4* W4 = (const float4*)W;
    int q = grp * 32 + lane;
    float4 acc = make_float4(0.f, 0.f, 0.f, 0.f);
    #pragma unroll 8
    for (int r = r0 + w; r < r1; r += 8) {
        float xv = sxp[r - r0];
        float4 wv = W4[(size_t)r * dout4 + q];
        acc.x += xv * wv.x; acc.y += xv * wv.y;
        acc.z += xv * wv.z; acc.w += xv * wv.w;
    }
    s_acc[w][lane] = acc;
    __syncthreads();
    if (tid < 32) {
        float4 t = s_acc[0][tid];
        #pragma unroll
        for (int i = 1; i < 8; i++) {
            float4 a = s_acc[i][tid];
            t.x += a.x; t.y += a.y; t.z += a.z; t.w += a.w;
        }
        ((float4*)dst)[grp * 32 + tid] = t;
    }
    __syncthreads();
}

// layernorm prologue: xfull = xr + sum(parts); LN'd vector -> sx[0..1023].
// If xw != null, also writes raw xfull (pre-LN) there.
__device__ __forceinline__ void ln_stage(const float* __restrict__ xr,
                                         const float* p1, int n1,
                                         const float* p2, int n2,
                                         const float* p3, int n3,
                                         const float* __restrict__ gamma,
                                         const float* __restrict__ beta,
                                         float* sx, float* swr, float* xw) {
    int tid = threadIdx.x, w = tid >> 5, lane = tid & 31;
    float4 xv = ldg4(xr + tid * 4);
    for (int s = 0; s < n1; s++) {
        float4 p = ldg4(p1 + s * Dm + tid * 4);
        xv.x += p.x; xv.y += p.y; xv.z += p.z; xv.w += p.w;
    }
    for (int s = 0; s < n2; s++) {
        float4 p = ldg4(p2 + s * Dm + tid * 4);
        xv.x += p.x; xv.y += p.y; xv.z += p.z; xv.w += p.w;
    }
    for (int s = 0; s < n3; s++) {
        float4 p = ldg4(p3 + s * Dm + tid * 4);
        xv.x += p.x; xv.y += p.y; xv.z += p.z; xv.w += p.w;
    }
    if (xw) ((float4*)xw)[tid] = xv;
    float s = xv.x + xv.y + xv.z + xv.w;
    #pragma unroll
    for (int m = 16; m >= 1; m >>= 1) s += __shfl_xor_sync(0xffffffffu, s, m);
    if (lane == 0) swr[w] = s;
    __syncthreads();
    float mean = 0.0f;
    #pragma unroll
    for (int i = 0; i < 8; i++) mean += swr[i];
    mean *= (1.0f / 1024.0f);
    float4 dv;
    dv.x = xv.x - mean; dv.y = xv.y - mean; dv.z = xv.z - mean; dv.w = xv.w - mean;
    float s2 = dv.x * dv.x + dv.y * dv.y + dv.z * dv.z + dv.w * dv.w;
    #pragma unroll
    for (int m = 16; m >= 1; m >>= 1) s2 += __shfl_xor_sync(0xffffffffu, s2, m);
    __syncthreads();
    if (lane == 0) swr[w] = s2;
    __syncthreads();
    float var = 0.0f;
    #pragma unroll
    for (int i = 0; i < 8; i++) var += swr[i];
    float rstd = rsqrtf(var * (1.0f / 1024.0f) + 1e-5f);
    float4 g4 = ((const float4*)gamma)[tid];
    float4 b4 = ((const float4*)beta)[tid];
    float4 o;
    o.x = dv.x * rstd * g4.x + b4.x;
    o.y = dv.y * rstd * g4.y + b4.y;
    o.z = dv.z * rstd * g4.z + b4.z;
    o.w = dv.w * rstd * g4.w + b4.w;
    ((float4*)sx)[tid] = o;
    __syncthreads();
}

__global__ void __launch_bounds__(256, 2)
mega(const int* __restrict__ ids, const float* __restrict__ enc,
     const float* __restrict__ past_k, const float* __restrict__ past_v,
     const float* __restrict__ emb, const float* __restrict__ pos,
     const float* __restrict__ ln1_g, const float* __restrict__ ln1_b,
     const float* __restrict__ wq_s, const float* __restrict__ wk_s,
     const float* __restrict__ wv_s, const float* __restrict__ wo_s,
     const float* __restrict__ ln2_g, const float* __restrict__ ln2_b,
     const float* __restrict__ wq_c, const float* __restrict__ wk_c,
     const float* __restrict__ wv_c, const float* __restrict__ wo_c,
     const float* __restrict__ ln3_g, const float* __restrict__ ln3_b,
     const float* __restrict__ w1, const float* __restrict__ w2,
     const float* __restrict__ lnf_g, const float* __restrict__ lnf_b,
     float* __restrict__ out) {
    __shared__ float sx[8448];
    __shared__ float4 s_acc[8][32];
    __shared__ float swr[8];
    __shared__ float sms[2];
    int bid = blockIdx.x, tid = threadIdx.x, w = tid >> 5, lane = tid & 31;
    const size_t DD = (size_t)Dm * Dm;
    const size_t KVL = (size_t)Hn * PASTn * DHn;

    // ---- embed ----
    if (bid == 0) {
        int id = ids[0];
        float4 a = *(const float4*)(emb + (size_t)id * Dm + tid * 4);
        float4 b = *(const float4*)(pos + (size_t)PASTn * Dm + tid * 4);
        a.x += b.x; a.y += b.y; a.z += b.z; a.w += b.w;
        ((float4*)g_X[0])[tid] = a;
    }
    gbar();

    for (int l = 0; l < Lnum; l++) {
        const float* Xr = g_X[l & 1];
        const float* pk = past_k + (size_t)l * KVL;   // <-- layer offset (R6 bug)
        const float* pv = past_v + (size_t)l * KVL;   // <-- layer offset (R6 bug)
        // ---- S1: LN1 + qkv (192 blocks) + x writeback ----
        if (bid < 192) {
            const float* xin = (l == 0) ? g_X[0] : g_X[(l - 1) & 1];
            float* xw = (l > 0 && bid == 0) ? g_X[l & 1] : nullptr;
            if (l == 0)
                ln_stage(xin, nullptr, 0, nullptr, 0, nullptr, 0,
                         ln1_g + l * Dm, ln1_b + l * Dm, sx, swr, xw);
            else
                ln_stage(xin, g_PB, 8, g_PE, 8, g_PG, 16,
                         ln1_g + l * Dm, ln1_b + l * Dm, sx, swr, xw);
            int gg = bid >> 3, rs = bid & 7;
            int m = gg >> 3, grp = gg & 7;
            const float* W = (m == 0 ? wq_s : (m == 1 ? wk_s : wv_s)) + l * DD;
            mv_core(W, 256, grp, rs * 128, rs * 128 + 128, sx + rs * 128,
                    g_PA + rs * 3072 + m * Dm, s_acc);
        }
        gbar();
        // ---- S2: split-KV self attention (256 blocks) ----
        if (bid < 256) {
            int h = bid >> 5, split = bid & 31, base = split * SPLEN;
            for (int i = tid; i < 384; i += 256) {
                int vec = i >> 7, c = i & 127;
                float a = 0.0f;
                #pragma unroll
                for (int s = 0; s < 8; s++)
                    a += ldg1(g_PA + s * 3072 + vec * Dm + h * DHn + c);
                sx[i] = a;  // [0..127]=q, [128..255]=k_new, [256..383]=v_new
            }
            __syncthreads();
            for (int pp = w; pp < SPLEN; pp += 8) {
                int p = base + pp;
                float4 k4 = (p < PASTn)
                    ? *(const float4*)(pk + ((size_t)h * PASTn + p) * DHn + lane * 4)
                    : ((float4*)(sx + 128))[lane];
                float4 q4 = ((float4*)sx)[lane];
                float d = k4.x * q4.x + k4.y * q4.y + k4.z * q4.z + k4.w * q4.w;
                #pragma unroll
                for (int m2 = 16; m2 >= 1; m2 >>= 1)
                    d += __shfl_xor_sync(0xffffffffu, d, m2);
                if (lane == 0) sx[384 + pp] = d * ATT_SCALE;
            }
            __syncthreads();
            if (tid < 32) {
                float v = (lane < SPLEN) ? sx[384 + lane] : -1e30f;
                float mm = v;
                #pragma unroll
                for (int m2 = 16; m2 >= 1; m2 >>= 1)
                    mm = fmaxf(mm, __shfl_xor_sync(0xffffffffu, mm, m2));
                float e = (lane < SPLEN) ? expf(v - mm) : 0.0f;
                float s = e;
                #pragma unroll
                for (int m2 = 16; m2 >= 1; m2 >>= 1)
                    s += __shfl_xor_sync(0xffffffffu, s, m2);
                if (lane < SPLEN) sx[384 + lane] = e;
                if (lane == 0) { sms[0] = mm; sms[1] = s; }
            }
            __syncthreads();
            int c = tid & 127, ph = tid >> 7;
            float acc = 0.0f;
            #pragma unroll
            for (int k = 0; k < 7; k++) {
                int pp = ph * 7 + k;
                int p = base + pp;
                float vv = (p < PASTn)
                    ? pv[((size_t)h * PASTn + p) * DHn + c] : sx[256 + c];
                acc += sx[384 + pp] * vv;
            }
            sx[512 + tid] = acc;
            __syncthreads();
            if (tid < 128) {
                g_po[(h * NSPLIT + split) * DHn + tid] = sx[512 + tid] + sx[640 + tid];
                if (tid == 0) {
                    g_pm[h * NSPLIT + split] = sms[0];
                    g_ps[h * NSPLIT + split] = sms[1];
                }
            }
        }
        gbar();
        // ---- S3: combine + wo_s (64 blocks) -> PB ----
        if (bid < 64) {
            int grp = bid >> 3, rs = bid & 7, r0 = rs * 128;
            sx[256 + tid] = ldg1(g_pm + tid);
            sx[512 + tid] = ldg1(g_ps + tid);
            __syncthreads();
            if (tid < 128) {
                int dim = r0 + tid, h = dim >> 7, c = dim & 127;
                float M = -1e30f;
                #pragma unroll
                for (int s = 0; s < NSPLIT; s++)
                    M = fmaxf(M, sx[256 + h * NSPLIT + s]);
                float S = 0.0f, o = 0.0f;
                #pragma unroll
                for (int s = 0; s < NSPLIT; s++) {
                    float wv = expf(sx[256 + h * NSPLIT + s] - M);
                    S += sx[512 + h * NSPLIT + s] * wv;
                    o += ldg1(g_po + (h * NSPLIT + s) * DHn + c) * wv;
                }
                sx[tid] = o / S;
            }
            __syncthreads();
            mv_core(wo_s + l * DD, 256, grp, r0, r0 + 128, sx, g_PB + rs * Dm, s_acc);
        }
        gbar();
        // ---- S4: LN2 + qc (64 blocks) -> PC ----
        if (bid < 64) {
            ln_stage(Xr, g_PB, 8, nullptr, 0, nullptr, 0,
                     ln2_g + l * Dm, ln2_b + l * Dm, sx, swr, nullptr);
            int grp = bid >> 3, rs = bid & 7;
            mv_core(wq_c + l * DD, 256, grp, rs * 128, rs * 128 + 128,
                    sx + rs * 128, g_PC + rs * Dm, s_acc);
        }
        gbar();
        // ---- S5: t[h][d] = qc_h . wk_c[d, h*128:+128] (128 blocks) ----
        if (bid < 128) {
            float4 a = ldg4(g_PC + tid * 4);
            #pragma unroll
            for (int s = 1; s < 8; s++) {
                float4 p = ldg4(g_PC + s * Dm + tid * 4);
                a.x += p.x; a.y += p.y; a.z += p.z; a.w += p.w;
            }
            ((float4*)sx)[tid] = a;
            __syncthreads();
            int d = bid * 8 + w;
            const float4* row = (const float4*)(wk_c + l * DD + (size_t)d * Dm);
            float acc[Hn];
            #pragma unroll
            for (int h = 0; h < Hn; h++) {
                float4 w4 = row[h * 32 + lane];
                float4 q4 = ((float4*)sx)[h * 32 + lane];
                acc[h] = w4.x * q4.x + w4.y * q4.y + w4.z * q4.z + w4.w * q4.w;
            }
            #pragma unroll
            for (int h = 0; h < Hn; h++) {
                #pragma unroll
                for (int m2 = 16; m2 >= 1; m2 >>= 1)
                    acc[h] += __shfl_xor_sync(0xffffffffu, acc[h], m2);
            }
            if (lane == 0) {
                #pragma unroll
                for (int h = 0; h < Hn; h++) g_t[h * Dm + d] = acc[h];
            }
        }
        gbar();
        // ---- S6: cross scores (55 blocks) ----
        if (bid < 55) {
            for (int i = tid; i < 2048; i += 256) ((float4*)sx)[i] = ldg4(g_t + i * 4);
            __syncthreads();
            int e = bid * 8 + w;
            if (e < ENCn) {
                const float4* erow = (const float4*)(enc + (size_t)e * Dm);
                float acc[Hn];
                #pragma unroll
                for (int h = 0; h < Hn; h++) acc[h] = 0.0f;
                #pragma unroll
                for (int r = 0; r < 8; r++) {
                    float4 e4 = erow[r * 32 + lane];
                    #pragma unroll
                    for (int h = 0; h < Hn; h++) {
                        float4 t4 = ((float4*)sx)[h * 256 + r * 32 + lane];
                        acc[h] += e4.x * t4.x + e4.y * t4.y + e4.z * t4.z + e4.w * t4.w;
                    }
                }
                #pragma unroll
                for (int h = 0; h < Hn; h++) {
                    #pragma unroll
                    for (int m2 = 16; m2 >= 1; m2 >>= 1)
                        acc[h] += __shfl_xor_sync(0xffffffffu, acc[h], m2);
                }
                if (lane == 0) {
                    #pragma unroll
                    for (int h = 0; h < Hn; h++)
                        g_sc[h * ENCn + e] = acc[h] * ATT_SCALE;
                }
            }
        }
        gbar();
        // ---- S7: u = softmax(sc) @ E (256 blocks) -> PU ----
        if (bid < 256) {
            int head = bid >> 5, rem = bid & 31, grp = rem >> 2, rs = rem & 3;
            const int ub0 = rs * 110;
            const int ub1 = (rs == 3) ? ENCn : (rs + 1) * 110;
            const float* scp = g_sc + head * ENCn;
            float v0 = (tid < ENCn) ? ldg1(scp + tid) : -1e30f;
            float v1 = (tid + 256 < ENCn) ? ldg1(scp + tid + 256) : -1e30f;
            float m = fmaxf(v0, v1);
            #pragma unroll
            for (int m2 = 16; m2 >= 1; m2 >>= 1)
                m = fmaxf(m, __shfl_xor_sync(0xffffffffu, m, m2));
            if (lane == 0) swr[w] = m;
            __syncthreads();
            float M = swr[0];
            #pragma unroll
            for (int i = 1; i < 8; i++) M = fmaxf(M, swr[i]);
            float e0 = (tid < ENCn) ? expf(v0 - M) : 0.0f;
            float e1 = (tid + 256 < ENCn) ? expf(v1 - M) : 0.0f;
            float s = e0 + e1;
            #pragma unroll
            for (int m2 = 16; m2 >= 1; m2 >>= 1)
                s += __shfl_xor_sync(0xffffffffu, s, m2);
            __syncthreads();
            if (lane == 0) swr[w] = s;
            __syncthreads();
            float S = 0.0f;
            #pragma unroll
            for (int i = 0; i < 8; i++) S += swr[i];
            float inv = 1.0f / S;
            for (int i = tid; i < ub1 - ub0; i += 256)
                sx[i] = expf(ldg1(scp + ub0 + i) - M) * inv;
            __syncthreads();
            mv_core(enc, 256, grp, ub0, ub1, sx, g_PU + (rs * Hn + head) * Dm, s_acc);
        }
        gbar();
        // ---- S8: att_o2 = u @ wv_c (64 blocks) -> PD ----
        if (bid < 64) {
            int grp = bid >> 3, rs = bid & 7, r0 = rs * 128;
            if (tid < 128) {
                float a = 0.0f;
                #pragma unroll
                for (int s = 0; s < 4; s++)
                    a += ldg1(g_PU + (s * Hn + grp) * Dm + r0 + tid);
                sx[tid] = a;
            }
            __syncthreads();
            mv_core(wv_c + l * DD, 256, grp, r0, r0 + 128, sx, g_PD + rs * Dm, s_acc);
        }
        gbar();
        // ---- S9: x += att_o2 @ wo_c (64 blocks) -> PE ----
        if (bid < 64) {
            int grp = bid >> 3, rs = bid & 7, r0 = rs * 128;
            if (tid < 128) {
                float a = 0.0f;
                #pragma unroll
                for (int s = 0; s < 8; s++) a += ldg1(g_PD + s * Dm + r0 + tid);
                sx[tid] = a;
            }
            __syncthreads();
            mv_core(wo_c + l * DD, 256, grp, r0, r0 + 128, sx, g_PE + rs * Dm, s_acc);
        }
        gbar();
        // ---- S10: LN3 + w1 (256 blocks) -> PF ----
        if (bid < 256) {
            ln_stage(Xr, g_PB, 8, g_PE, 8, nullptr, 0,
                     ln3_g + l * Dm, ln3_b + l * Dm, sx, swr, nullptr);
            int grp = bid >> 3, rs = bid & 7, r0 = rs * 128;
            mv_core(w1 + (size_t)l * Dm * Fn, 1024, grp, r0, r0 + 128,
                    sx + r0, g_PF + rs * Fn, s_acc);
        }
        gbar();
        // ---- S11: x += gelu(h1) @ w2 (128 blocks) -> PG ----
        if (bid < 128) {
            int grp = bid >> 4, rs = bid & 15, r0 = rs * 256;
            float a = 0.0f;
            #pragma unroll
            for (int s = 0; s < 8; s++) a += ldg1(g_PF + s * Fn + r0 + tid);
            sx[tid] = gelu_f(a);
            __syncthreads();
            mv_core(w2 + (size_t)l * Fn * Dm, 256, grp, r0, r0 + 256,
                    sx, g_PG + rs * Dm, s_acc);
        }
        gbar();
    }

    // ---- final LN + tied lm_head (all 296 blocks, warp per vocab row) ----
    ln_stage(g_X[1], g_PB, 8, g_PE, 8, g_PG, 16, lnf_g, lnf_b, sx, swr, nullptr);
    for (int v = bid * 8 + w; v < Vn; v += NB * 8) {
        const float4* erow = (const float4*)(emb + (size_t)v * Dm);
        float acc = 0.0f;
        #pragma unroll
        for (int r = 0; r < 8; r++) {
            float4 e4 = erow[r * 32 + lane];
            float4 h4 = ((float4*)sx)[r * 32 + lane];
            acc += e4.x * h4.x + e4.y * h4.y + e4.z * h4.z + e4.w * h4.w;
        }
        #pragma unroll
        for (int m2 = 16; m2 >= 1; m2 >>= 1)
            acc += __shfl_xor_sync(0xffffffffu, acc, m2);
        if (lane == 0) out[v] = acc;
    }
}

// ---------------- launch ----------------
extern "C" void kernel_launch(void* const* d_in, const int* in_sizes, int n_in,
                              void* d_out, int out_size) {
    mega<<<NB, 256>>>(
        (const int*)d_in[0], (const float*)d_in[1], (const float*)d_in[2],
        (const float*)d_in[3], (const float*)d_in[4], (const float*)d_in[5],
        (const float*)d_in[6], (const float*)d_in[7], (const float*)d_in[8],
        (const float*)d_in[9], (const float*)d_in[10], (const float*)d_in[11],
        (const float*)d_in[12], (const float*)d_in[13], (const float*)d_in[14],
        (const float*)d_in[15], (const float*)d_in[16], (const float*)d_in[17],
        (const float*)d_in[18], (const float*)d_in[19], (const float*)d_in[20],
        (const float*)d_in[21], (const float*)d_in[22], (const float*)d_in[23],
        (float*)d_out);
}